// round 2
// baseline (speedup 1.0000x reference)
#include <cuda_runtime.h>
#include <cuda_bf16.h>
#include <cstdint>

#define NN 50000
#define EE 800000
#define DIN 256
#define HH 128
#define AA 32

// ---------------- scratch (device globals; no allocation allowed) ----------------
__device__ float g_h   [(size_t)NN * HH];   // x @ W
__device__ float g_h0  [(size_t)NN * HH];   // relu(gat out)
__device__ float g_h1  [(size_t)NN * HH];   // fc1 out
__device__ float g_h2  [(size_t)NN * HH];   // fc2 out
__device__ float g_agg [(size_t)NN * HH];   // sum_e w * h[src]
__device__ float g_esrc[NN];
__device__ float g_edst[NN];
__device__ float g_denom[NN];
__device__ unsigned g_m[NN];                // ordered-uint encoded segment max
__device__ float g_e[EE];
__device__ float g_stats0[2 * HH];          // sum, sumsq (bn0)
__device__ float g_stats2[2 * HH];          // sum, sumsq (bn2)
__device__ float g_scale0[HH], g_shift0[HH];
__device__ float g_scale2[HH], g_shift2[HH];
__device__ int   g_is64;

// ---------------- helpers ----------------
__device__ __forceinline__ unsigned fenc(float f) {
    unsigned u = __float_as_uint(f);
    return (u & 0x80000000u) ? ~u : (u | 0x80000000u);
}
__device__ __forceinline__ float fdec(unsigned u) {
    u = (u & 0x80000000u) ? (u & 0x7fffffffu) : ~u;
    return __uint_as_float(u);
}
__device__ __forceinline__ void red_add_v4(float* ptr, float a, float b, float c, float d) {
    asm volatile("red.global.add.v4.f32 [%0], {%1,%2,%3,%4};"
                 :: "l"(ptr), "f"(a), "f"(b), "f"(c), "f"(d) : "memory");
}
__device__ __forceinline__ void load_edge(const void* ei, long i, int& src, int& dst) {
    if (g_is64) {
        const long long* p = (const long long*)ei;
        src = (int)p[i]; dst = (int)p[(long)EE + i];
    } else {
        const int* p = (const int*)ei;
        src = p[i]; dst = p[EE + i];
    }
}

// ---------------- kernels ----------------
// Detect whether edge_index is int64 (odd 32-bit words all zero) or int32.
__global__ void k_detect(const int* ei_words) {
    if (threadIdx.x == 0 && blockIdx.x == 0) {
        int nz = 0;
        for (int i = 1; i < 2048; i += 2) nz += (ei_words[i] != 0);
        g_is64 = (nz == 0) ? 1 : 0;
    }
}

// Zero / init all accumulators (must run every launch: graph replays reuse buffers)
__global__ void k_init() {
    long idx = (long)blockIdx.x * blockDim.x + threadIdx.x;
    long tot = (long)NN * HH;
    if (idx < tot) g_agg[idx] = 0.f;
    if (idx < NN) { g_denom[idx] = 0.f; g_m[idx] = 0u; }
    if (idx < 2 * HH) { g_stats0[idx] = 0.f; g_stats2[idx] = 0.f; }
}

// 128x128 tile SGEMM, N fixed = 128, optional per-k input affine transform and relu+bias epilogue.
#define BM 128
#define BN 128
#define BK 8
__global__ __launch_bounds__(256) void k_sgemm128(
    const float* __restrict__ A, const float* __restrict__ B, float* __restrict__ C,
    int M, int K,
    const float* __restrict__ in_scale, const float* __restrict__ in_shift,
    const float* __restrict__ bias, int do_relu)
{
    __shared__ float As[BK][BM];
    __shared__ float Bs[BK][BN];
    const int tid = threadIdx.x;
    const int blockRow = blockIdx.x * BM;
    const int trow = (tid >> 4) * 8;
    const int tcol = (tid & 15) * 8;
    const int aRow = tid >> 1;
    const int aCol = (tid & 1) * 4;
    const int bRow = tid >> 5;
    const int bCol = (tid & 31) * 4;

    float acc[8][8];
#pragma unroll
    for (int i = 0; i < 8; i++)
#pragma unroll
        for (int j = 0; j < 8; j++) acc[i][j] = 0.f;

    for (int k0 = 0; k0 < K; k0 += BK) {
        float4 av = make_float4(0.f, 0.f, 0.f, 0.f);
        int ar = blockRow + aRow;
        if (ar < M) av = *(const float4*)&A[(long)ar * K + k0 + aCol];
        if (in_scale) {
            float4 sc = *(const float4*)&in_scale[k0 + aCol];
            float4 sh = *(const float4*)&in_shift[k0 + aCol];
            av.x = fmaf(av.x, sc.x, sh.x);
            av.y = fmaf(av.y, sc.y, sh.y);
            av.z = fmaf(av.z, sc.z, sh.z);
            av.w = fmaf(av.w, sc.w, sh.w);
        }
        As[aCol + 0][aRow] = av.x;
        As[aCol + 1][aRow] = av.y;
        As[aCol + 2][aRow] = av.z;
        As[aCol + 3][aRow] = av.w;
        *(float4*)&Bs[bRow][bCol] = *(const float4*)&B[(long)(k0 + bRow) * BN + bCol];
        __syncthreads();
#pragma unroll
        for (int kk = 0; kk < BK; kk++) {
            float a[8], b[8];
            *(float4*)&a[0] = *(const float4*)&As[kk][trow];
            *(float4*)&a[4] = *(const float4*)&As[kk][trow + 4];
            *(float4*)&b[0] = *(const float4*)&Bs[kk][tcol];
            *(float4*)&b[4] = *(const float4*)&Bs[kk][tcol + 4];
#pragma unroll
            for (int i = 0; i < 8; i++)
#pragma unroll
                for (int j = 0; j < 8; j++) acc[i][j] = fmaf(a[i], b[j], acc[i][j]);
        }
        __syncthreads();
    }

#pragma unroll
    for (int i = 0; i < 8; i++) {
        int row = blockRow + trow + i;
        if (row < M) {
#pragma unroll
            for (int j = 0; j < 8; j += 4) {
                float4 v;
                v.x = acc[i][j + 0]; v.y = acc[i][j + 1];
                v.z = acc[i][j + 2]; v.w = acc[i][j + 3];
                if (bias) {
                    float4 bv = *(const float4*)&bias[tcol + j];
                    v.x += bv.x; v.y += bv.y; v.z += bv.z; v.w += bv.w;
                }
                if (do_relu) {
                    v.x = fmaxf(v.x, 0.f); v.y = fmaxf(v.y, 0.f);
                    v.z = fmaxf(v.z, 0.f); v.w = fmaxf(v.w, 0.f);
                }
                *(float4*)&C[(long)row * BN + tcol + j] = v;
            }
        }
    }
}

// per-node e_src / e_dst dots (warp per node)
__global__ void k_edot(const float* __restrict__ h, const float* __restrict__ a_src,
                       const float* __restrict__ a_dst) {
    int lane = threadIdx.x & 31;
    int n = blockIdx.x * 8 + (threadIdx.x >> 5);
    if (n >= NN) return;
    float4 hv = ((const float4*)h)[(long)n * 32 + lane];
    float4 as = ((const float4*)a_src)[lane];
    float4 ad = ((const float4*)a_dst)[lane];
    float s = hv.x * as.x + hv.y * as.y + hv.z * as.z + hv.w * as.w;
    float d = hv.x * ad.x + hv.y * ad.y + hv.z * ad.z + hv.w * ad.w;
#pragma unroll
    for (int o = 16; o; o >>= 1) {
        s += __shfl_xor_sync(0xffffffffu, s, o);
        d += __shfl_xor_sync(0xffffffffu, d, o);
    }
    if (lane == 0) { g_esrc[n] = s; g_edst[n] = d; }
}

// edge pass 1: e = leakyrelu(e_src[src]+e_dst[dst]); segment max into g_m[dst]
__global__ void k_edge1(const void* __restrict__ ei) {
    long i = (long)blockIdx.x * blockDim.x + threadIdx.x;
    if (i >= EE) return;
    int src, dst;
    load_edge(ei, i, src, dst);
    float e = g_esrc[src] + g_edst[dst];
    e = (e >= 0.f) ? e : 0.2f * e;
    g_e[i] = e;
    atomicMax(&g_m[dst], fenc(e));
}

// edge pass 2 (warp per edge): w = exp(e-m[dst]); denom[dst]+=w; agg[dst] += w*h[src]
__global__ void k_edge2(const void* __restrict__ ei) {
    int lane = threadIdx.x & 31;
    long i = (long)blockIdx.x * 8 + (threadIdx.x >> 5);
    if (i >= EE) return;
    int src, dst;
    load_edge(ei, i, src, dst);
    float e = g_e[i];
    float mm = fdec(g_m[dst]);
    float w = __expf(e - mm);
    if (lane == 0) atomicAdd(&g_denom[dst], w);
    float4 hv = ((const float4*)g_h)[(long)src * 32 + lane];
    red_add_v4(&g_agg[(long)dst * HH + lane * 4], w * hv.x, w * hv.y, w * hv.z, w * hv.w);
}

// h0 = relu(agg / max(denom,1e-16) + b_gat)
__global__ void k_h0(const float* __restrict__ b_gat) {
    long idx = (long)blockIdx.x * blockDim.x + threadIdx.x;
    if (idx >= (long)NN * HH) return;
    int n = idx >> 7, c = idx & 127;
    float d = fmaxf(g_denom[n], 1e-16f);
    float v = g_agg[idx] / d + b_gat[c];
    g_h0[idx] = fmaxf(v, 0.f);
}

// per-feature sum / sumsq
__global__ void k_stats(const float* __restrict__ h, float* __restrict__ stats) {
    int t = threadIdx.x; // 128
    float s = 0.f, sq = 0.f;
    for (int n = blockIdx.x; n < NN; n += gridDim.x) {
        float v = h[(long)n * HH + t];
        s += v; sq += v * v;
    }
    atomicAdd(&stats[t], s);
    atomicAdd(&stats[HH + t], sq);
}

__global__ void k_finalize_bn(const float* __restrict__ stats,
                              const float* __restrict__ gamma, const float* __restrict__ beta,
                              float* __restrict__ scale, float* __restrict__ shift) {
    int t = threadIdx.x; // 128
    float mu = stats[t] / (float)NN;
    float var = stats[HH + t] / (float)NN - mu * mu;
    float sc = gamma[t] * rsqrtf(var + 1e-5f);
    scale[t] = sc;
    shift[t] = beta[t] - mu * sc;
}

// final: (bn2(h2)) @ W3 + b3 -> softmax -> out   (warp per node)
__global__ void k_final(const float* __restrict__ h2,
                        const float* __restrict__ W3, const float* __restrict__ b3,
                        float* __restrict__ out) {
    __shared__ float W3s[HH * AA];
    __shared__ float b3s[AA];
    int t = threadIdx.x; // 256
    for (int i = t; i < HH * AA; i += 256) W3s[i] = W3[i];
    if (t < AA) b3s[t] = b3[t];
    __syncthreads();
    int lane = t & 31;
    int n = blockIdx.x * 8 + (t >> 5);
    if (n >= NN) return;
    float hreg[4];
#pragma unroll
    for (int j = 0; j < 4; j++) {
        int c = j * 32 + lane;
        hreg[j] = fmaf(h2[(long)n * HH + c], g_scale2[c], g_shift2[c]);
    }
    float acc = b3s[lane];
#pragma unroll
    for (int k = 0; k < HH; k++) {
        float hv = __shfl_sync(0xffffffffu, hreg[k >> 5], k & 31);
        acc = fmaf(hv, W3s[k * AA + lane], acc);
    }
    float mx = acc;
#pragma unroll
    for (int o = 16; o; o >>= 1) mx = fmaxf(mx, __shfl_xor_sync(0xffffffffu, mx, o));
    float p = __expf(acc - mx);
    float s = p;
#pragma unroll
    for (int o = 16; o; o >>= 1) s += __shfl_xor_sync(0xffffffffu, s, o);
    out[(long)n * AA + lane] = p / s;
}

// ---------------- launch ----------------
extern "C" void kernel_launch(void* const* d_in, const int* in_sizes, int n_in,
                              void* d_out, int out_size) {
    const float* x     = (const float*)d_in[0];
    const void*  ei    = d_in[1];
    const float* W     = (const float*)d_in[2];
    const float* a_src = (const float*)d_in[3];
    const float* a_dst = (const float*)d_in[4];
    const float* b_gat = (const float*)d_in[5];
    const float* g0    = (const float*)d_in[6];
    const float* beta0 = (const float*)d_in[7];
    const float* W1    = (const float*)d_in[8];
    const float* b1    = (const float*)d_in[9];
    const float* W2    = (const float*)d_in[10];
    const float* b2    = (const float*)d_in[11];
    const float* g2    = (const float*)d_in[12];
    const float* beta2 = (const float*)d_in[13];
    const float* W3    = (const float*)d_in[14];
    const float* b3    = (const float*)d_in[15];
    float* out = (float*)d_out;

    float *p_h, *p_h0, *p_h1, *p_h2, *p_stats0, *p_stats2;
    float *p_scale0, *p_shift0, *p_scale2, *p_shift2;
    cudaGetSymbolAddress((void**)&p_h, g_h);
    cudaGetSymbolAddress((void**)&p_h0, g_h0);
    cudaGetSymbolAddress((void**)&p_h1, g_h1);
    cudaGetSymbolAddress((void**)&p_h2, g_h2);
    cudaGetSymbolAddress((void**)&p_stats0, g_stats0);
    cudaGetSymbolAddress((void**)&p_stats2, g_stats2);
    cudaGetSymbolAddress((void**)&p_scale0, g_scale0);
    cudaGetSymbolAddress((void**)&p_shift0, g_shift0);
    cudaGetSymbolAddress((void**)&p_scale2, g_scale2);
    cudaGetSymbolAddress((void**)&p_shift2, g_shift2);

    const int gemmGrid = (NN + BM - 1) / BM;  // 391

    k_detect<<<1, 32>>>((const int*)ei);
    k_init<<<(NN * HH + 255) / 256, 256>>>();
    k_sgemm128<<<gemmGrid, 256>>>(x, W, p_h, NN, DIN, nullptr, nullptr, nullptr, 0);
    k_edot<<<(NN + 7) / 8, 256>>>(p_h, a_src, a_dst);
    k_edge1<<<(EE + 255) / 256, 256>>>(ei);
    k_edge2<<<(EE + 7) / 8, 256>>>(ei);
    k_h0<<<(NN * HH + 255) / 256, 256>>>(b_gat);
    k_stats<<<512, 128>>>(p_h0, p_stats0);
    k_finalize_bn<<<1, 128>>>(p_stats0, g0, beta0, p_scale0, p_shift0);
    k_sgemm128<<<gemmGrid, 256>>>(p_h0, W1, p_h1, NN, HH, p_scale0, p_shift0, b1, 1);
    k_sgemm128<<<gemmGrid, 256>>>(p_h1, W2, p_h2, NN, HH, nullptr, nullptr, b2, 1);
    k_stats<<<512, 128>>>(p_h2, p_stats2);
    k_finalize_bn<<<1, 128>>>(p_stats2, g2, beta2, p_scale2, p_shift2);
    k_final<<<(NN + 7) / 8, 256>>>(p_h2, W3, b3, out);
}

// round 3
// speedup vs baseline: 1.1879x; 1.1879x over previous
#include <cuda_runtime.h>
#include <cuda_bf16.h>
#include <cstdint>

#define NN 50000
#define EE 800000
#define DIN 256
#define HH 128
#define AA 32

// ---------------- scratch (device globals; no allocation allowed) ----------------
__device__ float g_h   [(size_t)NN * HH];   // x @ W
__device__ float g_h0  [(size_t)NN * HH];   // relu(gat out)
__device__ float g_h1  [(size_t)NN * HH];   // fc1 out
__device__ float g_h2  [(size_t)NN * HH];   // fc2 out
__device__ float g_agg [(size_t)NN * HH];   // sum_e w * h[src]
__device__ float g_esrc[NN];
__device__ float g_edst[NN];
__device__ float g_denom[NN];
__device__ unsigned g_m[NN];                // ordered-uint encoded segment max
__device__ float g_e[EE];
__device__ float g_stats0[2 * HH];
__device__ float g_stats2[2 * HH];
__device__ float g_scale0[HH], g_shift0[HH];
__device__ float g_scale2[HH], g_shift2[HH];
__device__ float g_Bhi[DIN * HH];           // split weight buffers (max K=256)
__device__ float g_Blo[DIN * HH];
__device__ int   g_is64;

// ---------------- helpers ----------------
__device__ __forceinline__ unsigned fenc(float f) {
    unsigned u = __float_as_uint(f);
    return (u & 0x80000000u) ? ~u : (u | 0x80000000u);
}
__device__ __forceinline__ float fdec(unsigned u) {
    u = (u & 0x80000000u) ? (u & 0x7fffffffu) : ~u;
    return __uint_as_float(u);
}
__device__ __forceinline__ void red_add_v4(float* ptr, float a, float b, float c, float d) {
    asm volatile("red.global.add.v4.f32 [%0], {%1,%2,%3,%4};"
                 :: "l"(ptr), "f"(a), "f"(b), "f"(c), "f"(d) : "memory");
}
__device__ __forceinline__ void load_edge(const void* ei, long i, int& src, int& dst) {
    if (g_is64) {
        const long long* p = (const long long*)ei;
        src = (int)p[i]; dst = (int)p[(long)EE + i];
    } else {
        const int* p = (const int*)ei;
        src = p[i]; dst = p[EE + i];
    }
}
__device__ __forceinline__ void tf32_split(float v, float& hi, float& lo) {
    unsigned h;
    asm("cvt.rna.tf32.f32 %0, %1;" : "=r"(h) : "f"(v));
    float fh = __uint_as_float(h);
    float r = v - fh;
    unsigned l;
    asm("cvt.rna.tf32.f32 %0, %1;" : "=r"(l) : "f"(r));
    hi = fh; lo = __uint_as_float(l);
}
__device__ __forceinline__ void mma_tf32(float* c, const unsigned* a, unsigned b0, unsigned b1) {
    asm volatile(
        "mma.sync.aligned.m16n8k8.row.col.f32.tf32.tf32.f32 "
        "{%0,%1,%2,%3}, {%4,%5,%6,%7}, {%8,%9}, {%0,%1,%2,%3};"
        : "+f"(c[0]), "+f"(c[1]), "+f"(c[2]), "+f"(c[3])
        : "r"(a[0]), "r"(a[1]), "r"(a[2]), "r"(a[3]), "r"(b0), "r"(b1));
}

// ---------------- kernels ----------------
__global__ void k_detect(const int* ei_words) {
    if (threadIdx.x == 0 && blockIdx.x == 0) {
        int nz = 0;
        for (int i = 1; i < 2048; i += 2) nz += (ei_words[i] != 0);
        g_is64 = (nz == 0) ? 1 : 0;
    }
}

__global__ void k_init() {
    long idx = (long)blockIdx.x * blockDim.x + threadIdx.x;
    long tot = (long)NN * HH;
    if (idx < tot) g_agg[idx] = 0.f;
    if (idx < NN) { g_denom[idx] = 0.f; g_m[idx] = 0u; }
    if (idx < 2 * HH) { g_stats0[idx] = 0.f; g_stats2[idx] = 0.f; }
}

// split weight matrix into tf32 hi/lo
__global__ void k_splitB(const float* __restrict__ B, int n) {
    int i = blockIdx.x * 256 + threadIdx.x;
    if (i < n) {
        float hi, lo;
        tf32_split(B[i], hi, lo);
        g_Bhi[i] = hi; g_Blo[i] = lo;
    }
}

// ------------- 3xTF32 tensor-core GEMM: C[M,128] = A[M,K] @ B[K,128] -------------
#define GBM 128
#define GBN 128
#define GBK 16
#define SPAD 4   // row stride 132 floats = 528B = 33*16B (keeps float4 alignment)

__global__ __launch_bounds__(256, 2) void k_gemm_tf32(
    const float* __restrict__ A,
    const float* __restrict__ Bhi, const float* __restrict__ Blo,
    float* __restrict__ C, int M, int K,
    const float* __restrict__ in_scale, const float* __restrict__ in_shift,
    const float* __restrict__ bias, int do_relu)
{
    __shared__ float As_hi[GBK][GBM + SPAD];
    __shared__ float As_lo[GBK][GBM + SPAD];
    __shared__ float Bs_hi[GBK][GBN + SPAD];
    __shared__ float Bs_lo[GBK][GBN + SPAD];

    const int tid = threadIdx.x;
    const int warp = tid >> 5, lane = tid & 31;
    const int g = lane >> 2, q = lane & 3;
    const int wm = (warp & 3) * 32;       // warp M offset (4 warps along M)
    const int wn = (warp >> 2) * 64;      // warp N offset (2 warps along N)
    const int blockRow = blockIdx.x * GBM;

    // A staging: thread loads 8 floats of row arow at cols [acol, acol+8)
    const int arow = tid >> 1;
    const int acol = (tid & 1) * 8;
    // B staging: thread copies 8 floats: row bk, cols [bn, bn+8)
    const int bk = tid >> 4;
    const int bn = (tid & 15) * 8;

    float c[2][8][4];
#pragma unroll
    for (int mt = 0; mt < 2; mt++)
#pragma unroll
        for (int nt = 0; nt < 8; nt++)
#pragma unroll
            for (int j = 0; j < 4; j++) c[mt][nt][j] = 0.f;

    for (int k0 = 0; k0 < K; k0 += GBK) {
        // ---- stage A (with optional affine), split to tf32 hi/lo ----
        {
            float v[8];
#pragma unroll
            for (int j = 0; j < 8; j++) v[j] = 0.f;
            int r = blockRow + arow;
            if (r < M) {
                float4 v0 = *(const float4*)&A[(long)r * K + k0 + acol];
                float4 v1 = *(const float4*)&A[(long)r * K + k0 + acol + 4];
                v[0] = v0.x; v[1] = v0.y; v[2] = v0.z; v[3] = v0.w;
                v[4] = v1.x; v[5] = v1.y; v[6] = v1.z; v[7] = v1.w;
            }
            if (in_scale) {
#pragma unroll
                for (int j = 0; j < 8; j++)
                    v[j] = fmaf(v[j], in_scale[k0 + acol + j], in_shift[k0 + acol + j]);
            }
#pragma unroll
            for (int j = 0; j < 8; j++) {
                float hi, lo;
                tf32_split(v[j], hi, lo);
                As_hi[acol + j][arow] = hi;
                As_lo[acol + j][arow] = lo;
            }
        }
        // ---- stage B (already split in global) ----
        {
            const float4* ph = (const float4*)&Bhi[(long)(k0 + bk) * GBN + bn];
            const float4* pl = (const float4*)&Blo[(long)(k0 + bk) * GBN + bn];
            *(float4*)&Bs_hi[bk][bn]     = ph[0];
            *(float4*)&Bs_hi[bk][bn + 4] = ph[1];
            *(float4*)&Bs_lo[bk][bn]     = pl[0];
            *(float4*)&Bs_lo[bk][bn + 4] = pl[1];
        }
        __syncthreads();

#pragma unroll
        for (int ks = 0; ks < GBK; ks += 8) {
            unsigned ah[2][4], al[2][4];
#pragma unroll
            for (int mt = 0; mt < 2; mt++) {
                int m = wm + mt * 16;
                ah[mt][0] = __float_as_uint(As_hi[ks + q][m + g]);
                ah[mt][1] = __float_as_uint(As_hi[ks + q][m + g + 8]);
                ah[mt][2] = __float_as_uint(As_hi[ks + q + 4][m + g]);
                ah[mt][3] = __float_as_uint(As_hi[ks + q + 4][m + g + 8]);
                al[mt][0] = __float_as_uint(As_lo[ks + q][m + g]);
                al[mt][1] = __float_as_uint(As_lo[ks + q][m + g + 8]);
                al[mt][2] = __float_as_uint(As_lo[ks + q + 4][m + g]);
                al[mt][3] = __float_as_uint(As_lo[ks + q + 4][m + g + 8]);
            }
#pragma unroll
            for (int nt = 0; nt < 8; nt++) {
                int n = wn + nt * 8 + g;
                unsigned bh0 = __float_as_uint(Bs_hi[ks + q][n]);
                unsigned bh1 = __float_as_uint(Bs_hi[ks + q + 4][n]);
                unsigned bl0 = __float_as_uint(Bs_lo[ks + q][n]);
                unsigned bl1 = __float_as_uint(Bs_lo[ks + q + 4][n]);
#pragma unroll
                for (int mt = 0; mt < 2; mt++) {
                    mma_tf32(c[mt][nt], ah[mt], bh0, bh1);  // hi*hi
                    mma_tf32(c[mt][nt], al[mt], bh0, bh1);  // lo*hi
                    mma_tf32(c[mt][nt], ah[mt], bl0, bl1);  // hi*lo
                }
            }
        }
        __syncthreads();
    }

    // ---- epilogue ----
#pragma unroll
    for (int mt = 0; mt < 2; mt++) {
#pragma unroll
        for (int nt = 0; nt < 8; nt++) {
            int col = wn + nt * 8 + q * 2;
            float b0 = 0.f, b1 = 0.f;
            if (bias) { b0 = bias[col]; b1 = bias[col + 1]; }
#pragma unroll
            for (int half = 0; half < 2; half++) {
                int row = blockRow + wm + mt * 16 + g + half * 8;
                if (row < M) {
                    float v0 = c[mt][nt][half * 2 + 0] + b0;
                    float v1 = c[mt][nt][half * 2 + 1] + b1;
                    if (do_relu) { v0 = fmaxf(v0, 0.f); v1 = fmaxf(v1, 0.f); }
                    float2 o; o.x = v0; o.y = v1;
                    *(float2*)&C[(long)row * GBN + col] = o;
                }
            }
        }
    }
}

// per-node e_src / e_dst dots (warp per node)
__global__ void k_edot(const float* __restrict__ h, const float* __restrict__ a_src,
                       const float* __restrict__ a_dst) {
    int lane = threadIdx.x & 31;
    int n = blockIdx.x * 8 + (threadIdx.x >> 5);
    if (n >= NN) return;
    float4 hv = ((const float4*)h)[(long)n * 32 + lane];
    float4 as = ((const float4*)a_src)[lane];
    float4 ad = ((const float4*)a_dst)[lane];
    float s = hv.x * as.x + hv.y * as.y + hv.z * as.z + hv.w * as.w;
    float d = hv.x * ad.x + hv.y * ad.y + hv.z * ad.z + hv.w * ad.w;
#pragma unroll
    for (int o = 16; o; o >>= 1) {
        s += __shfl_xor_sync(0xffffffffu, s, o);
        d += __shfl_xor_sync(0xffffffffu, d, o);
    }
    if (lane == 0) { g_esrc[n] = s; g_edst[n] = d; }
}

__global__ void k_edge1(const void* __restrict__ ei) {
    long i = (long)blockIdx.x * blockDim.x + threadIdx.x;
    if (i >= EE) return;
    int src, dst;
    load_edge(ei, i, src, dst);
    float e = g_esrc[src] + g_edst[dst];
    e = (e >= 0.f) ? e : 0.2f * e;
    g_e[i] = e;
    atomicMax(&g_m[dst], fenc(e));
}

__global__ void k_edge2(const void* __restrict__ ei) {
    int lane = threadIdx.x & 31;
    long i = (long)blockIdx.x * 8 + (threadIdx.x >> 5);
    if (i >= EE) return;
    int src, dst;
    load_edge(ei, i, src, dst);
    float e = g_e[i];
    float mm = fdec(g_m[dst]);
    float w = __expf(e - mm);
    if (lane == 0) atomicAdd(&g_denom[dst], w);
    float4 hv = ((const float4*)g_h)[(long)src * 32 + lane];
    red_add_v4(&g_agg[(long)dst * HH + lane * 4], w * hv.x, w * hv.y, w * hv.z, w * hv.w);
}

__global__ void k_h0(const float* __restrict__ b_gat) {
    long idx = (long)blockIdx.x * blockDim.x + threadIdx.x;
    if (idx >= (long)NN * HH) return;
    int n = idx >> 7, c = idx & 127;
    float d = fmaxf(g_denom[n], 1e-16f);
    float v = g_agg[idx] / d + b_gat[c];
    g_h0[idx] = fmaxf(v, 0.f);
}

__global__ void k_stats(const float* __restrict__ h, float* __restrict__ stats) {
    int t = threadIdx.x; // 128
    float s = 0.f, sq = 0.f;
    for (int n = blockIdx.x; n < NN; n += gridDim.x) {
        float v = h[(long)n * HH + t];
        s += v; sq += v * v;
    }
    atomicAdd(&stats[t], s);
    atomicAdd(&stats[HH + t], sq);
}

__global__ void k_finalize_bn(const float* __restrict__ stats,
                              const float* __restrict__ gamma, const float* __restrict__ beta,
                              float* __restrict__ scale, float* __restrict__ shift) {
    int t = threadIdx.x; // 128
    float mu = stats[t] / (float)NN;
    float var = stats[HH + t] / (float)NN - mu * mu;
    float sc = gamma[t] * rsqrtf(var + 1e-5f);
    scale[t] = sc;
    shift[t] = beta[t] - mu * sc;
}

__global__ void k_final(const float* __restrict__ h2,
                        const float* __restrict__ W3, const float* __restrict__ b3,
                        float* __restrict__ out) {
    __shared__ float W3s[HH * AA];
    __shared__ float b3s[AA];
    int t = threadIdx.x; // 256
    for (int i = t; i < HH * AA; i += 256) W3s[i] = W3[i];
    if (t < AA) b3s[t] = b3[t];
    __syncthreads();
    int lane = t & 31;
    int n = blockIdx.x * 8 + (t >> 5);
    if (n >= NN) return;
    float hreg[4];
#pragma unroll
    for (int j = 0; j < 4; j++) {
        int c = j * 32 + lane;
        hreg[j] = fmaf(h2[(long)n * HH + c], g_scale2[c], g_shift2[c]);
    }
    float acc = b3s[lane];
#pragma unroll
    for (int k = 0; k < HH; k++) {
        float hv = __shfl_sync(0xffffffffu, hreg[k >> 5], k & 31);
        acc = fmaf(hv, W3s[k * AA + lane], acc);
    }
    float mx = acc;
#pragma unroll
    for (int o = 16; o; o >>= 1) mx = fmaxf(mx, __shfl_xor_sync(0xffffffffu, mx, o));
    float p = __expf(acc - mx);
    float s = p;
#pragma unroll
    for (int o = 16; o; o >>= 1) s += __shfl_xor_sync(0xffffffffu, s, o);
    out[(long)n * AA + lane] = p / s;
}

// ---------------- launch ----------------
extern "C" void kernel_launch(void* const* d_in, const int* in_sizes, int n_in,
                              void* d_out, int out_size) {
    const float* x     = (const float*)d_in[0];
    const void*  ei    = d_in[1];
    const float* W     = (const float*)d_in[2];
    const float* a_src = (const float*)d_in[3];
    const float* a_dst = (const float*)d_in[4];
    const float* b_gat = (const float*)d_in[5];
    const float* g0    = (const float*)d_in[6];
    const float* beta0 = (const float*)d_in[7];
    const float* W1    = (const float*)d_in[8];
    const float* b1    = (const float*)d_in[9];
    const float* W2    = (const float*)d_in[10];
    const float* b2    = (const float*)d_in[11];
    const float* g2    = (const float*)d_in[12];
    const float* beta2 = (const float*)d_in[13];
    const float* W3    = (const float*)d_in[14];
    const float* b3    = (const float*)d_in[15];
    float* out = (float*)d_out;

    float *p_h, *p_h0, *p_h1, *p_h2, *p_stats0, *p_stats2;
    float *p_scale0, *p_shift0, *p_scale2, *p_shift2, *p_bhi, *p_blo;
    cudaGetSymbolAddress((void**)&p_h, g_h);
    cudaGetSymbolAddress((void**)&p_h0, g_h0);
    cudaGetSymbolAddress((void**)&p_h1, g_h1);
    cudaGetSymbolAddress((void**)&p_h2, g_h2);
    cudaGetSymbolAddress((void**)&p_stats0, g_stats0);
    cudaGetSymbolAddress((void**)&p_stats2, g_stats2);
    cudaGetSymbolAddress((void**)&p_scale0, g_scale0);
    cudaGetSymbolAddress((void**)&p_shift0, g_shift0);
    cudaGetSymbolAddress((void**)&p_scale2, g_scale2);
    cudaGetSymbolAddress((void**)&p_shift2, g_shift2);
    cudaGetSymbolAddress((void**)&p_bhi, g_Bhi);
    cudaGetSymbolAddress((void**)&p_blo, g_Blo);

    const int gemmGrid = (NN + GBM - 1) / GBM;  // 391

    k_detect<<<1, 32>>>((const int*)ei);
    k_init<<<(NN * HH + 255) / 256, 256>>>();

    // GEMM1: h = x @ W  (K=256)
    k_splitB<<<(DIN * HH + 255) / 256, 256>>>(W, DIN * HH);
    k_gemm_tf32<<<gemmGrid, 256>>>(x, p_bhi, p_blo, p_h, NN, DIN,
                                   nullptr, nullptr, nullptr, 0);

    k_edot<<<(NN + 7) / 8, 256>>>(p_h, a_src, a_dst);
    k_edge1<<<(EE + 255) / 256, 256>>>(ei);
    k_edge2<<<(EE + 7) / 8, 256>>>(ei);
    k_h0<<<(NN * HH + 255) / 256, 256>>>(b_gat);
    k_stats<<<512, 128>>>(p_h0, p_stats0);
    k_finalize_bn<<<1, 128>>>(p_stats0, g0, beta0, p_scale0, p_shift0);

    // GEMM2: h1 = relu(bn0(h0) @ W1 + b1)  (K=128, bn fused into A-load)
    k_splitB<<<(HH * HH + 255) / 256, 256>>>(W1, HH * HH);
    k_gemm_tf32<<<gemmGrid, 256>>>(p_h0, p_bhi, p_blo, p_h1, NN, HH,
                                   p_scale0, p_shift0, b1, 1);

    // GEMM3: h2 = relu(h1 @ W2 + b2)
    k_splitB<<<(HH * HH + 255) / 256, 256>>>(W2, HH * HH);
    k_gemm_tf32<<<gemmGrid, 256>>>(p_h1, p_bhi, p_blo, p_h2, NN, HH,
                                   nullptr, nullptr, b2, 1);

    k_stats<<<512, 128>>>(p_h2, p_stats2);
    k_finalize_bn<<<1, 128>>>(p_stats2, g2, beta2, p_scale2, p_shift2);
    k_final<<<(NN + 7) / 8, 256>>>(p_h2, W3, b3, out);
}

// round 4
// speedup vs baseline: 1.3730x; 1.1558x over previous
#include <cuda_runtime.h>
#include <cuda_bf16.h>
#include <cstdint>

#define NN 50000
#define EE 800000
#define DIN 256
#define HH 128
#define AA 32
#define NB_SCAN 196   // ceil(50000/256)

// ---------------- scratch (device globals) ----------------
__device__ float g_h   [(size_t)NN * HH];   // x @ W
__device__ float g_h0  [(size_t)NN * HH];   // relu(gat out)
__device__ float g_h1  [(size_t)NN * HH];
__device__ float g_h2  [(size_t)NN * HH];
__device__ float g_esrc[NN];
__device__ float g_edst[NN];
__device__ int   g_rowcnt[NN];
__device__ int   g_rowoff[NN + 1];
__device__ int   g_cursor[NN];
__device__ int   g_partial[256];
__device__ int   g_csr_src[EE];
__device__ float g_csr_e[EE];
__device__ float g_stats0[2 * HH];
__device__ float g_stats2[2 * HH];
__device__ float g_scale0[HH], g_shift0[HH];
__device__ float g_scale2[HH], g_shift2[HH];
__device__ float g_Bhi[DIN * HH];
__device__ float g_Blo[DIN * HH];
__device__ int   g_is64;

// ---------------- helpers ----------------
__device__ __forceinline__ void load_edge(const void* ei, long i, int& src, int& dst) {
    if (g_is64) {
        const long long* p = (const long long*)ei;
        src = (int)p[i]; dst = (int)p[(long)EE + i];
    } else {
        const int* p = (const int*)ei;
        src = p[i]; dst = p[EE + i];
    }
}
__device__ __forceinline__ void tf32_split(float v, float& hi, float& lo) {
    unsigned h;
    asm("cvt.rna.tf32.f32 %0, %1;" : "=r"(h) : "f"(v));
    float fh = __uint_as_float(h);
    float r = v - fh;
    unsigned l;
    asm("cvt.rna.tf32.f32 %0, %1;" : "=r"(l) : "f"(r));
    hi = fh; lo = __uint_as_float(l);
}
__device__ __forceinline__ void mma_tf32(float* c, const unsigned* a, unsigned b0, unsigned b1) {
    asm volatile(
        "mma.sync.aligned.m16n8k8.row.col.f32.tf32.tf32.f32 "
        "{%0,%1,%2,%3}, {%4,%5,%6,%7}, {%8,%9}, {%0,%1,%2,%3};"
        : "+f"(c[0]), "+f"(c[1]), "+f"(c[2]), "+f"(c[3])
        : "r"(a[0]), "r"(a[1]), "r"(a[2]), "r"(a[3]), "r"(b0), "r"(b1));
}

// ---------------- misc kernels ----------------
__global__ void k_detect(const int* ei_words) {
    if (threadIdx.x == 0 && blockIdx.x == 0) {
        int nz = 0;
        for (int i = 1; i < 2048; i += 2) nz += (ei_words[i] != 0);
        g_is64 = (nz == 0) ? 1 : 0;
    }
}

__global__ void k_init() {
    int idx = blockIdx.x * blockDim.x + threadIdx.x;
    if (idx < NN) g_rowcnt[idx] = 0;
    if (idx < 2 * HH) { g_stats0[idx] = 0.f; g_stats2[idx] = 0.f; }
}

__global__ void k_splitB(const float* __restrict__ B, int n) {
    int i = blockIdx.x * 256 + threadIdx.x;
    if (i < n) {
        float hi, lo;
        tf32_split(B[i], hi, lo);
        g_Bhi[i] = hi; g_Blo[i] = lo;
    }
}

// ------------- 3xTF32 tensor-core GEMM with register prefetch -------------
#define GBM 128
#define GBN 128
#define GBK 16
#define SPAD 4

__global__ __launch_bounds__(256, 2) void k_gemm_tf32(
    const float* __restrict__ A,
    const float* __restrict__ Bhi, const float* __restrict__ Blo,
    float* __restrict__ C, int M, int K,
    const float* __restrict__ in_scale, const float* __restrict__ in_shift,
    const float* __restrict__ bias, int do_relu)
{
    __shared__ float As_hi[GBK][GBM + SPAD];
    __shared__ float As_lo[GBK][GBM + SPAD];
    __shared__ float Bs_hi[GBK][GBN + SPAD];
    __shared__ float Bs_lo[GBK][GBN + SPAD];

    const int tid = threadIdx.x;
    const int warp = tid >> 5, lane = tid & 31;
    const int g = lane >> 2, q = lane & 3;
    const int wm = (warp & 3) * 32;
    const int wn = (warp >> 2) * 64;
    const int blockRow = blockIdx.x * GBM;

    const int arow = tid >> 1;
    const int acol = (tid & 1) * 8;
    const int bk = tid >> 4;
    const int bn = (tid & 15) * 8;

    const int aRowGlobal = blockRow + arow;
    const bool aValid = aRowGlobal < M;

    float c[2][8][4];
#pragma unroll
    for (int mt = 0; mt < 2; mt++)
#pragma unroll
        for (int nt = 0; nt < 8; nt++)
#pragma unroll
            for (int j = 0; j < 4; j++) c[mt][nt][j] = 0.f;

    float av[8], bh[8], bl[8];

    // ---- prefetch tile 0 ----
    {
        const int k0 = 0;
#pragma unroll
        for (int j = 0; j < 8; j++) av[j] = 0.f;
        if (aValid) {
            float4 v0 = *(const float4*)&A[(long)aRowGlobal * K + k0 + acol];
            float4 v1 = *(const float4*)&A[(long)aRowGlobal * K + k0 + acol + 4];
            av[0] = v0.x; av[1] = v0.y; av[2] = v0.z; av[3] = v0.w;
            av[4] = v1.x; av[5] = v1.y; av[6] = v1.z; av[7] = v1.w;
        }
        if (in_scale) {
#pragma unroll
            for (int j = 0; j < 8; j++)
                av[j] = fmaf(av[j], in_scale[k0 + acol + j], in_shift[k0 + acol + j]);
        }
        float4 h0 = *(const float4*)&Bhi[(long)(k0 + bk) * GBN + bn];
        float4 h1 = *(const float4*)&Bhi[(long)(k0 + bk) * GBN + bn + 4];
        float4 l0 = *(const float4*)&Blo[(long)(k0 + bk) * GBN + bn];
        float4 l1 = *(const float4*)&Blo[(long)(k0 + bk) * GBN + bn + 4];
        bh[0]=h0.x; bh[1]=h0.y; bh[2]=h0.z; bh[3]=h0.w;
        bh[4]=h1.x; bh[5]=h1.y; bh[6]=h1.z; bh[7]=h1.w;
        bl[0]=l0.x; bl[1]=l0.y; bl[2]=l0.z; bl[3]=l0.w;
        bl[4]=l1.x; bl[5]=l1.y; bl[6]=l1.z; bl[7]=l1.w;
    }

    const int ntiles = K / GBK;
    for (int t = 0; t < ntiles; t++) {
        // ---- store prefetched tile to smem ----
#pragma unroll
        for (int j = 0; j < 8; j++) {
            float hi, lo;
            tf32_split(av[j], hi, lo);
            As_hi[acol + j][arow] = hi;
            As_lo[acol + j][arow] = lo;
        }
        *(float4*)&Bs_hi[bk][bn]     = make_float4(bh[0], bh[1], bh[2], bh[3]);
        *(float4*)&Bs_hi[bk][bn + 4] = make_float4(bh[4], bh[5], bh[6], bh[7]);
        *(float4*)&Bs_lo[bk][bn]     = make_float4(bl[0], bl[1], bl[2], bl[3]);
        *(float4*)&Bs_lo[bk][bn + 4] = make_float4(bl[4], bl[5], bl[6], bl[7]);
        __syncthreads();

        // ---- issue prefetch for tile t+1 (overlaps MMA below) ----
        if (t + 1 < ntiles) {
            const int k0 = (t + 1) * GBK;
#pragma unroll
            for (int j = 0; j < 8; j++) av[j] = 0.f;
            if (aValid) {
                float4 v0 = *(const float4*)&A[(long)aRowGlobal * K + k0 + acol];
                float4 v1 = *(const float4*)&A[(long)aRowGlobal * K + k0 + acol + 4];
                av[0] = v0.x; av[1] = v0.y; av[2] = v0.z; av[3] = v0.w;
                av[4] = v1.x; av[5] = v1.y; av[6] = v1.z; av[7] = v1.w;
            }
            if (in_scale) {
#pragma unroll
                for (int j = 0; j < 8; j++)
                    av[j] = fmaf(av[j], in_scale[k0 + acol + j], in_shift[k0 + acol + j]);
            }
            float4 h0 = *(const float4*)&Bhi[(long)(k0 + bk) * GBN + bn];
            float4 h1 = *(const float4*)&Bhi[(long)(k0 + bk) * GBN + bn + 4];
            float4 l0 = *(const float4*)&Blo[(long)(k0 + bk) * GBN + bn];
            float4 l1 = *(const float4*)&Blo[(long)(k0 + bk) * GBN + bn + 4];
            bh[0]=h0.x; bh[1]=h0.y; bh[2]=h0.z; bh[3]=h0.w;
            bh[4]=h1.x; bh[5]=h1.y; bh[6]=h1.z; bh[7]=h1.w;
            bl[0]=l0.x; bl[1]=l0.y; bl[2]=l0.z; bl[3]=l0.w;
            bl[4]=l1.x; bl[5]=l1.y; bl[6]=l1.z; bl[7]=l1.w;
        }

        // ---- MMA over current tile ----
#pragma unroll
        for (int ks = 0; ks < GBK; ks += 8) {
            unsigned ah[2][4], al[2][4];
#pragma unroll
            for (int mt = 0; mt < 2; mt++) {
                int m = wm + mt * 16;
                ah[mt][0] = __float_as_uint(As_hi[ks + q][m + g]);
                ah[mt][1] = __float_as_uint(As_hi[ks + q][m + g + 8]);
                ah[mt][2] = __float_as_uint(As_hi[ks + q + 4][m + g]);
                ah[mt][3] = __float_as_uint(As_hi[ks + q + 4][m + g + 8]);
                al[mt][0] = __float_as_uint(As_lo[ks + q][m + g]);
                al[mt][1] = __float_as_uint(As_lo[ks + q][m + g + 8]);
                al[mt][2] = __float_as_uint(As_lo[ks + q + 4][m + g]);
                al[mt][3] = __float_as_uint(As_lo[ks + q + 4][m + g + 8]);
            }
#pragma unroll
            for (int nt = 0; nt < 8; nt++) {
                int n = wn + nt * 8 + g;
                unsigned bh0 = __float_as_uint(Bs_hi[ks + q][n]);
                unsigned bh1 = __float_as_uint(Bs_hi[ks + q + 4][n]);
                unsigned bl0 = __float_as_uint(Bs_lo[ks + q][n]);
                unsigned bl1 = __float_as_uint(Bs_lo[ks + q + 4][n]);
#pragma unroll
                for (int mt = 0; mt < 2; mt++) {
                    mma_tf32(c[mt][nt], ah[mt], bh0, bh1);
                    mma_tf32(c[mt][nt], al[mt], bh0, bh1);
                    mma_tf32(c[mt][nt], ah[mt], bl0, bl1);
                }
            }
        }
        __syncthreads();
    }

    // ---- epilogue ----
#pragma unroll
    for (int mt = 0; mt < 2; mt++) {
#pragma unroll
        for (int nt = 0; nt < 8; nt++) {
            int col = wn + nt * 8 + q * 2;
            float b0 = 0.f, b1 = 0.f;
            if (bias) { b0 = bias[col]; b1 = bias[col + 1]; }
#pragma unroll
            for (int half = 0; half < 2; half++) {
                int row = blockRow + wm + mt * 16 + g + half * 8;
                if (row < M) {
                    float v0 = c[mt][nt][half * 2 + 0] + b0;
                    float v1 = c[mt][nt][half * 2 + 1] + b1;
                    if (do_relu) { v0 = fmaxf(v0, 0.f); v1 = fmaxf(v1, 0.f); }
                    float2 o; o.x = v0; o.y = v1;
                    *(float2*)&C[(long)row * GBN + col] = o;
                }
            }
        }
    }
}

// per-node e_src / e_dst dots
__global__ void k_edot(const float* __restrict__ h, const float* __restrict__ a_src,
                       const float* __restrict__ a_dst) {
    int lane = threadIdx.x & 31;
    int n = blockIdx.x * 8 + (threadIdx.x >> 5);
    if (n >= NN) return;
    float4 hv = ((const float4*)h)[(long)n * 32 + lane];
    float4 as = ((const float4*)a_src)[lane];
    float4 ad = ((const float4*)a_dst)[lane];
    float s = hv.x * as.x + hv.y * as.y + hv.z * as.z + hv.w * as.w;
    float d = hv.x * ad.x + hv.y * ad.y + hv.z * ad.z + hv.w * ad.w;
#pragma unroll
    for (int o = 16; o; o >>= 1) {
        s += __shfl_xor_sync(0xffffffffu, s, o);
        d += __shfl_xor_sync(0xffffffffu, d, o);
    }
    if (lane == 0) { g_esrc[n] = s; g_edst[n] = d; }
}

// ---------------- CSR build ----------------
__global__ void k_hist(const void* __restrict__ ei) {
    long i = (long)blockIdx.x * blockDim.x + threadIdx.x;
    if (i >= EE) return;
    int src, dst;
    load_edge(ei, i, src, dst);
    atomicAdd(&g_rowcnt[dst], 1);
}

__global__ void k_scan1() {
    __shared__ int s[256];
    int idx = blockIdx.x * 256 + threadIdx.x;
    int v = (idx < NN) ? g_rowcnt[idx] : 0;
    s[threadIdx.x] = v;
    __syncthreads();
    for (int o = 128; o; o >>= 1) {
        if (threadIdx.x < o) s[threadIdx.x] += s[threadIdx.x + o];
        __syncthreads();
    }
    if (threadIdx.x == 0) g_partial[blockIdx.x] = s[0];
}

__global__ void k_scan2() {
    __shared__ int s[256];
    int t = threadIdx.x;
    int v = (t < NB_SCAN) ? g_partial[t] : 0;
    s[t] = v;
    __syncthreads();
#pragma unroll
    for (int d = 1; d < 256; d <<= 1) {
        int x = (t >= d) ? s[t - d] : 0;
        __syncthreads();
        s[t] += x;
        __syncthreads();
    }
    if (t < NB_SCAN) g_partial[t] = s[t] - v;  // exclusive
}

__global__ void k_scan3() {
    __shared__ int s[256];
    int t = threadIdx.x;
    int idx = blockIdx.x * 256 + t;
    int v = (idx < NN) ? g_rowcnt[idx] : 0;
    s[t] = v;
    __syncthreads();
#pragma unroll
    for (int d = 1; d < 256; d <<= 1) {
        int x = (t >= d) ? s[t - d] : 0;
        __syncthreads();
        s[t] += x;
        __syncthreads();
    }
    if (idx < NN) {
        int off = g_partial[blockIdx.x] + s[t] - v;
        g_rowoff[idx] = off;
        g_cursor[idx] = off;
        if (idx == NN - 1) g_rowoff[NN] = off + v;
    }
}

__global__ void k_scatter(const void* __restrict__ ei) {
    long i = (long)blockIdx.x * blockDim.x + threadIdx.x;
    if (i >= EE) return;
    int src, dst;
    load_edge(ei, i, src, dst);
    float e = g_esrc[src] + g_edst[dst];
    e = (e >= 0.f) ? e : 0.2f * e;
    int slot = atomicAdd(&g_cursor[dst], 1);
    g_csr_src[slot] = src;
    g_csr_e[slot] = e;
}

// ---------------- fused GAT aggregation: warp per dst node ----------------
__global__ __launch_bounds__(256) void k_agg(const float* __restrict__ b_gat) {
    int lane = threadIdx.x & 31;
    int n = blockIdx.x * 8 + (threadIdx.x >> 5);
    if (n >= NN) return;
    int beg = g_rowoff[n], end = g_rowoff[n + 1];

    // pass 1: segment max
    float m = -3.402823466e+38f;
    for (int i = beg + lane; i < end; i += 32) m = fmaxf(m, g_csr_e[i]);
#pragma unroll
    for (int o = 16; o; o >>= 1) m = fmaxf(m, __shfl_xor_sync(0xffffffffu, m, o));

    // pass 2: weighted aggregate
    float4 acc = make_float4(0.f, 0.f, 0.f, 0.f);
    float den = 0.f;
    for (int base = beg; base < end; base += 32) {
        int cnt = min(32, end - base);
        float ee = (base + lane < end) ? g_csr_e[base + lane] : 0.f;
        int ss = (base + lane < end) ? g_csr_src[base + lane] : 0;
        for (int j = 0; j < cnt; j++) {
            float e = __shfl_sync(0xffffffffu, ee, j);
            int s = __shfl_sync(0xffffffffu, ss, j);
            float w = __expf(e - m);
            den += w;
            float4 hv = ((const float4*)g_h)[(long)s * 32 + lane];
            acc.x = fmaf(w, hv.x, acc.x);
            acc.y = fmaf(w, hv.y, acc.y);
            acc.z = fmaf(w, hv.z, acc.z);
            acc.w = fmaf(w, hv.w, acc.w);
        }
    }
    float inv = 1.f / fmaxf(den, 1e-16f);
    float4 bg = ((const float4*)b_gat)[lane];
    float4 o;
    o.x = fmaxf(fmaf(acc.x, inv, bg.x), 0.f);
    o.y = fmaxf(fmaf(acc.y, inv, bg.y), 0.f);
    o.z = fmaxf(fmaf(acc.z, inv, bg.z), 0.f);
    o.w = fmaxf(fmaf(acc.w, inv, bg.w), 0.f);
    ((float4*)g_h0)[(long)n * 32 + lane] = o;
}

// ---------------- BN stats ----------------
__global__ void k_stats(const float* __restrict__ h, float* __restrict__ stats) {
    int t = threadIdx.x; // 128
    float s = 0.f, sq = 0.f;
    for (int n = blockIdx.x; n < NN; n += gridDim.x) {
        float v = h[(long)n * HH + t];
        s += v; sq += v * v;
    }
    atomicAdd(&stats[t], s);
    atomicAdd(&stats[HH + t], sq);
}

__global__ void k_finalize_bn(const float* __restrict__ stats,
                              const float* __restrict__ gamma, const float* __restrict__ beta,
                              float* __restrict__ scale, float* __restrict__ shift) {
    int t = threadIdx.x; // 128
    float mu = stats[t] / (float)NN;
    float var = stats[HH + t] / (float)NN - mu * mu;
    float sc = gamma[t] * rsqrtf(var + 1e-5f);
    scale[t] = sc;
    shift[t] = beta[t] - mu * sc;
}

// ---------------- final head ----------------
__global__ void k_final(const float* __restrict__ h2,
                        const float* __restrict__ W3, const float* __restrict__ b3,
                        float* __restrict__ out) {
    __shared__ float W3s[HH * AA];
    __shared__ float b3s[AA];
    int t = threadIdx.x; // 256
    for (int i = t; i < HH * AA; i += 256) W3s[i] = W3[i];
    if (t < AA) b3s[t] = b3[t];
    __syncthreads();
    int lane = t & 31;
    int n = blockIdx.x * 8 + (t >> 5);
    if (n >= NN) return;
    float hreg[4];
#pragma unroll
    for (int j = 0; j < 4; j++) {
        int c = j * 32 + lane;
        hreg[j] = fmaf(h2[(long)n * HH + c], g_scale2[c], g_shift2[c]);
    }
    float acc = b3s[lane];
#pragma unroll
    for (int k = 0; k < HH; k++) {
        float hv = __shfl_sync(0xffffffffu, hreg[k >> 5], k & 31);
        acc = fmaf(hv, W3s[k * AA + lane], acc);
    }
    float mx = acc;
#pragma unroll
    for (int o = 16; o; o >>= 1) mx = fmaxf(mx, __shfl_xor_sync(0xffffffffu, mx, o));
    float p = __expf(acc - mx);
    float s = p;
#pragma unroll
    for (int o = 16; o; o >>= 1) s += __shfl_xor_sync(0xffffffffu, s, o);
    out[(long)n * AA + lane] = p / s;
}

// ---------------- launch ----------------
extern "C" void kernel_launch(void* const* d_in, const int* in_sizes, int n_in,
                              void* d_out, int out_size) {
    const float* x     = (const float*)d_in[0];
    const void*  ei    = d_in[1];
    const float* W     = (const float*)d_in[2];
    const float* a_src = (const float*)d_in[3];
    const float* a_dst = (const float*)d_in[4];
    const float* b_gat = (const float*)d_in[5];
    const float* g0    = (const float*)d_in[6];
    const float* beta0 = (const float*)d_in[7];
    const float* W1    = (const float*)d_in[8];
    const float* b1    = (const float*)d_in[9];
    const float* W2    = (const float*)d_in[10];
    const float* b2    = (const float*)d_in[11];
    const float* g2    = (const float*)d_in[12];
    const float* beta2 = (const float*)d_in[13];
    const float* W3    = (const float*)d_in[14];
    const float* b3    = (const float*)d_in[15];
    float* out = (float*)d_out;

    float *p_h, *p_h0, *p_h1, *p_h2, *p_stats0, *p_stats2;
    float *p_scale0, *p_shift0, *p_scale2, *p_shift2, *p_bhi, *p_blo;
    cudaGetSymbolAddress((void**)&p_h, g_h);
    cudaGetSymbolAddress((void**)&p_h0, g_h0);
    cudaGetSymbolAddress((void**)&p_h1, g_h1);
    cudaGetSymbolAddress((void**)&p_h2, g_h2);
    cudaGetSymbolAddress((void**)&p_stats0, g_stats0);
    cudaGetSymbolAddress((void**)&p_stats2, g_stats2);
    cudaGetSymbolAddress((void**)&p_scale0, g_scale0);
    cudaGetSymbolAddress((void**)&p_shift0, g_shift0);
    cudaGetSymbolAddress((void**)&p_scale2, g_scale2);
    cudaGetSymbolAddress((void**)&p_shift2, g_shift2);
    cudaGetSymbolAddress((void**)&p_bhi, g_Bhi);
    cudaGetSymbolAddress((void**)&p_blo, g_Blo);

    const int gemmGrid = (NN + GBM - 1) / GBM;  // 391

    k_detect<<<1, 32>>>((const int*)ei);
    k_init<<<(NN + 255) / 256, 256>>>();

    // GEMM1: h = x @ W (K=256)
    k_splitB<<<(DIN * HH + 255) / 256, 256>>>(W, DIN * HH);
    k_gemm_tf32<<<gemmGrid, 256>>>(x, p_bhi, p_blo, p_h, NN, DIN,
                                   nullptr, nullptr, nullptr, 0);

    k_edot<<<(NN + 7) / 8, 256>>>(p_h, a_src, a_dst);

    // CSR build + fused aggregation
    k_hist<<<(EE + 255) / 256, 256>>>(ei);
    k_scan1<<<NB_SCAN, 256>>>();
    k_scan2<<<1, 256>>>();
    k_scan3<<<NB_SCAN, 256>>>();
    k_scatter<<<(EE + 255) / 256, 256>>>(ei);
    k_agg<<<(NN + 7) / 8, 256>>>(b_gat);

    k_stats<<<512, 128>>>(p_h0, p_stats0);
    k_finalize_bn<<<1, 128>>>(p_stats0, g0, beta0, p_scale0, p_shift0);

    // GEMM2: h1 = relu(bn0(h0) @ W1 + b1)
    k_splitB<<<(HH * HH + 255) / 256, 256>>>(W1, HH * HH);
    k_gemm_tf32<<<gemmGrid, 256>>>(p_h0, p_bhi, p_blo, p_h1, NN, HH,
                                   p_scale0, p_shift0, b1, 1);

    // GEMM3: h2 = relu(h1 @ W2 + b2)
    k_splitB<<<(HH * HH + 255) / 256, 256>>>(W2, HH * HH);
    k_gemm_tf32<<<gemmGrid, 256>>>(p_h1, p_bhi, p_blo, p_h2, NN, HH,
                                   nullptr, nullptr, b2, 1);

    k_stats<<<512, 128>>>(p_h2, p_stats2);
    k_finalize_bn<<<1, 128>>>(p_stats2, g2, beta2, p_scale2, p_shift2);
    k_final<<<(NN + 7) / 8, 256>>>(p_h2, W3, b3, out);
}

// round 5
// speedup vs baseline: 1.3754x; 1.0017x over previous
#include <cuda_runtime.h>
#include <cuda_bf16.h>
#include <cstdint>

#define NN 50000
#define EE 800000
#define DIN 256
#define HH 128
#define AA 32
#define NB_SCAN 196   // ceil(50000/256)

// ---------------- scratch (device globals) ----------------
__device__ float g_h   [(size_t)NN * HH];   // x @ W
__device__ float g_h0  [(size_t)NN * HH];   // relu(gat out)
__device__ float g_h1  [(size_t)NN * HH];
__device__ float g_h2  [(size_t)NN * HH];
__device__ float g_esrc[NN];
__device__ float g_edst[NN];
__device__ int   g_rowcnt[NN];
__device__ int   g_rowoff[NN + 1];
__device__ int   g_cursor[NN];
__device__ int   g_partial[256];
__device__ int   g_csr_src[EE];
__device__ float g_csr_e[EE];
__device__ float g_stats0[2 * HH];
__device__ float g_stats2[2 * HH];
__device__ float g_scale0[HH], g_shift0[HH];
__device__ float g_scale2[HH], g_shift2[HH];
__device__ float g_Bhi[DIN * HH];
__device__ float g_Blo[DIN * HH];
__device__ int   g_is64;

// ---------------- helpers ----------------
__device__ __forceinline__ void load_edge(const void* ei, long i, int& src, int& dst) {
    if (g_is64) {
        const long long* p = (const long long*)ei;
        src = (int)p[i]; dst = (int)p[(long)EE + i];
    } else {
        const int* p = (const int*)ei;
        src = p[i]; dst = p[EE + i];
    }
}
__device__ __forceinline__ void tf32_split(float v, float& hi, float& lo) {
    unsigned h;
    asm("cvt.rna.tf32.f32 %0, %1;" : "=r"(h) : "f"(v));
    float fh = __uint_as_float(h);
    float r = v - fh;
    unsigned l;
    asm("cvt.rna.tf32.f32 %0, %1;" : "=r"(l) : "f"(r));
    hi = fh; lo = __uint_as_float(l);
}
__device__ __forceinline__ void mma_tf32(float* c, const unsigned* a, unsigned b0, unsigned b1) {
    asm volatile(
        "mma.sync.aligned.m16n8k8.row.col.f32.tf32.tf32.f32 "
        "{%0,%1,%2,%3}, {%4,%5,%6,%7}, {%8,%9}, {%0,%1,%2,%3};"
        : "+f"(c[0]), "+f"(c[1]), "+f"(c[2]), "+f"(c[3])
        : "r"(a[0]), "r"(a[1]), "r"(a[2]), "r"(a[3]), "r"(b0), "r"(b1));
}

// ---------------- misc kernels ----------------
__global__ void k_detect(const int* ei_words) {
    if (threadIdx.x == 0 && blockIdx.x == 0) {
        int nz = 0;
        for (int i = 1; i < 2048; i += 2) nz += (ei_words[i] != 0);
        g_is64 = (nz == 0) ? 1 : 0;
    }
}

__global__ void k_init() {
    int idx = blockIdx.x * blockDim.x + threadIdx.x;
    if (idx < NN) g_rowcnt[idx] = 0;
    if (idx < 2 * HH) { g_stats0[idx] = 0.f; g_stats2[idx] = 0.f; }
}

__global__ void k_splitB(const float* __restrict__ B, int n) {
    int i = blockIdx.x * 256 + threadIdx.x;
    if (i < n) {
        float hi, lo;
        tf32_split(B[i], hi, lo);
        g_Bhi[i] = hi; g_Blo[i] = lo;
    }
}

// ------------- 3xTF32 tensor-core GEMM with register prefetch -------------
#define GBM 128
#define GBN 128
#define GBK 16
#define SPAD 4

__global__ __launch_bounds__(256, 2) void k_gemm_tf32(
    const float* __restrict__ A,
    const float* __restrict__ Bhi, const float* __restrict__ Blo,
    float* __restrict__ C, int M, int K,
    const float* __restrict__ in_scale, const float* __restrict__ in_shift,
    const float* __restrict__ bias, int do_relu)
{
    __shared__ float As_hi[GBK][GBM + SPAD];
    __shared__ float As_lo[GBK][GBM + SPAD];
    __shared__ float Bs_hi[GBK][GBN + SPAD];
    __shared__ float Bs_lo[GBK][GBN + SPAD];

    const int tid = threadIdx.x;
    const int warp = tid >> 5, lane = tid & 31;
    const int g = lane >> 2, q = lane & 3;
    const int wm = (warp & 3) * 32;
    const int wn = (warp >> 2) * 64;
    const int blockRow = blockIdx.x * GBM;

    const int arow = tid >> 1;
    const int acol = (tid & 1) * 8;
    const int bk = tid >> 4;
    const int bn = (tid & 15) * 8;

    const int aRowGlobal = blockRow + arow;
    const bool aValid = aRowGlobal < M;

    float c[2][8][4];
#pragma unroll
    for (int mt = 0; mt < 2; mt++)
#pragma unroll
        for (int nt = 0; nt < 8; nt++)
#pragma unroll
            for (int j = 0; j < 4; j++) c[mt][nt][j] = 0.f;

    float av[8], bh[8], bl[8];

    // ---- prefetch tile 0 ----
    {
        const int k0 = 0;
#pragma unroll
        for (int j = 0; j < 8; j++) av[j] = 0.f;
        if (aValid) {
            float4 v0 = *(const float4*)&A[(long)aRowGlobal * K + k0 + acol];
            float4 v1 = *(const float4*)&A[(long)aRowGlobal * K + k0 + acol + 4];
            av[0] = v0.x; av[1] = v0.y; av[2] = v0.z; av[3] = v0.w;
            av[4] = v1.x; av[5] = v1.y; av[6] = v1.z; av[7] = v1.w;
        }
        if (in_scale) {
#pragma unroll
            for (int j = 0; j < 8; j++)
                av[j] = fmaf(av[j], in_scale[k0 + acol + j], in_shift[k0 + acol + j]);
        }
        float4 h0 = *(const float4*)&Bhi[(long)(k0 + bk) * GBN + bn];
        float4 h1 = *(const float4*)&Bhi[(long)(k0 + bk) * GBN + bn + 4];
        float4 l0 = *(const float4*)&Blo[(long)(k0 + bk) * GBN + bn];
        float4 l1 = *(const float4*)&Blo[(long)(k0 + bk) * GBN + bn + 4];
        bh[0]=h0.x; bh[1]=h0.y; bh[2]=h0.z; bh[3]=h0.w;
        bh[4]=h1.x; bh[5]=h1.y; bh[6]=h1.z; bh[7]=h1.w;
        bl[0]=l0.x; bl[1]=l0.y; bl[2]=l0.z; bl[3]=l0.w;
        bl[4]=l1.x; bl[5]=l1.y; bl[6]=l1.z; bl[7]=l1.w;
    }

    const int ntiles = K / GBK;
    for (int t = 0; t < ntiles; t++) {
        // ---- store prefetched tile to smem ----
#pragma unroll
        for (int j = 0; j < 8; j++) {
            float hi, lo;
            tf32_split(av[j], hi, lo);
            As_hi[acol + j][arow] = hi;
            As_lo[acol + j][arow] = lo;
        }
        *(float4*)&Bs_hi[bk][bn]     = make_float4(bh[0], bh[1], bh[2], bh[3]);
        *(float4*)&Bs_hi[bk][bn + 4] = make_float4(bh[4], bh[5], bh[6], bh[7]);
        *(float4*)&Bs_lo[bk][bn]     = make_float4(bl[0], bl[1], bl[2], bl[3]);
        *(float4*)&Bs_lo[bk][bn + 4] = make_float4(bl[4], bl[5], bl[6], bl[7]);
        __syncthreads();

        // ---- issue prefetch for tile t+1 (overlaps MMA below) ----
        if (t + 1 < ntiles) {
            const int k0 = (t + 1) * GBK;
#pragma unroll
            for (int j = 0; j < 8; j++) av[j] = 0.f;
            if (aValid) {
                float4 v0 = *(const float4*)&A[(long)aRowGlobal * K + k0 + acol];
                float4 v1 = *(const float4*)&A[(long)aRowGlobal * K + k0 + acol + 4];
                av[0] = v0.x; av[1] = v0.y; av[2] = v0.z; av[3] = v0.w;
                av[4] = v1.x; av[5] = v1.y; av[6] = v1.z; av[7] = v1.w;
            }
            if (in_scale) {
#pragma unroll
                for (int j = 0; j < 8; j++)
                    av[j] = fmaf(av[j], in_scale[k0 + acol + j], in_shift[k0 + acol + j]);
            }
            float4 h0 = *(const float4*)&Bhi[(long)(k0 + bk) * GBN + bn];
            float4 h1 = *(const float4*)&Bhi[(long)(k0 + bk) * GBN + bn + 4];
            float4 l0 = *(const float4*)&Blo[(long)(k0 + bk) * GBN + bn];
            float4 l1 = *(const float4*)&Blo[(long)(k0 + bk) * GBN + bn + 4];
            bh[0]=h0.x; bh[1]=h0.y; bh[2]=h0.z; bh[3]=h0.w;
            bh[4]=h1.x; bh[5]=h1.y; bh[6]=h1.z; bh[7]=h1.w;
            bl[0]=l0.x; bl[1]=l0.y; bl[2]=l0.z; bl[3]=l0.w;
            bl[4]=l1.x; bl[5]=l1.y; bl[6]=l1.z; bl[7]=l1.w;
        }

        // ---- MMA over current tile ----
#pragma unroll
        for (int ks = 0; ks < GBK; ks += 8) {
            unsigned ah[2][4], al[2][4];
#pragma unroll
            for (int mt = 0; mt < 2; mt++) {
                int m = wm + mt * 16;
                ah[mt][0] = __float_as_uint(As_hi[ks + q][m + g]);
                ah[mt][1] = __float_as_uint(As_hi[ks + q][m + g + 8]);
                ah[mt][2] = __float_as_uint(As_hi[ks + q + 4][m + g]);
                ah[mt][3] = __float_as_uint(As_hi[ks + q + 4][m + g + 8]);
                al[mt][0] = __float_as_uint(As_lo[ks + q][m + g]);
                al[mt][1] = __float_as_uint(As_lo[ks + q][m + g + 8]);
                al[mt][2] = __float_as_uint(As_lo[ks + q + 4][m + g]);
                al[mt][3] = __float_as_uint(As_lo[ks + q + 4][m + g + 8]);
            }
#pragma unroll
            for (int nt = 0; nt < 8; nt++) {
                int n = wn + nt * 8 + g;
                unsigned bh0 = __float_as_uint(Bs_hi[ks + q][n]);
                unsigned bh1 = __float_as_uint(Bs_hi[ks + q + 4][n]);
                unsigned bl0 = __float_as_uint(Bs_lo[ks + q][n]);
                unsigned bl1 = __float_as_uint(Bs_lo[ks + q + 4][n]);
#pragma unroll
                for (int mt = 0; mt < 2; mt++) {
                    mma_tf32(c[mt][nt], ah[mt], bh0, bh1);
                    mma_tf32(c[mt][nt], al[mt], bh0, bh1);
                    mma_tf32(c[mt][nt], ah[mt], bl0, bl1);
                }
            }
        }
        __syncthreads();
    }

    // ---- epilogue ----
#pragma unroll
    for (int mt = 0; mt < 2; mt++) {
#pragma unroll
        for (int nt = 0; nt < 8; nt++) {
            int col = wn + nt * 8 + q * 2;
            float b0 = 0.f, b1 = 0.f;
            if (bias) { b0 = bias[col]; b1 = bias[col + 1]; }
#pragma unroll
            for (int half = 0; half < 2; half++) {
                int row = blockRow + wm + mt * 16 + g + half * 8;
                if (row < M) {
                    float v0 = c[mt][nt][half * 2 + 0] + b0;
                    float v1 = c[mt][nt][half * 2 + 1] + b1;
                    if (do_relu) { v0 = fmaxf(v0, 0.f); v1 = fmaxf(v1, 0.f); }
                    float2 o; o.x = v0; o.y = v1;
                    *(float2*)&C[(long)row * GBN + col] = o;
                }
            }
        }
    }
}

// per-node e_src / e_dst dots
__global__ void k_edot(const float* __restrict__ h, const float* __restrict__ a_src,
                       const float* __restrict__ a_dst) {
    int lane = threadIdx.x & 31;
    int n = blockIdx.x * 8 + (threadIdx.x >> 5);
    if (n >= NN) return;
    float4 hv = ((const float4*)h)[(long)n * 32 + lane];
    float4 as = ((const float4*)a_src)[lane];
    float4 ad = ((const float4*)a_dst)[lane];
    float s = hv.x * as.x + hv.y * as.y + hv.z * as.z + hv.w * as.w;
    float d = hv.x * ad.x + hv.y * ad.y + hv.z * ad.z + hv.w * ad.w;
#pragma unroll
    for (int o = 16; o; o >>= 1) {
        s += __shfl_xor_sync(0xffffffffu, s, o);
        d += __shfl_xor_sync(0xffffffffu, d, o);
    }
    if (lane == 0) { g_esrc[n] = s; g_edst[n] = d; }
}

// ---------------- CSR build ----------------
__global__ void k_hist(const void* __restrict__ ei) {
    long i = (long)blockIdx.x * blockDim.x + threadIdx.x;
    if (i >= EE) return;
    int src, dst;
    load_edge(ei, i, src, dst);
    atomicAdd(&g_rowcnt[dst], 1);
}

__global__ void k_scan1() {
    __shared__ int s[256];
    int idx = blockIdx.x * 256 + threadIdx.x;
    int v = (idx < NN) ? g_rowcnt[idx] : 0;
    s[threadIdx.x] = v;
    __syncthreads();
    for (int o = 128; o; o >>= 1) {
        if (threadIdx.x < o) s[threadIdx.x] += s[threadIdx.x + o];
        __syncthreads();
    }
    if (threadIdx.x == 0) g_partial[blockIdx.x] = s[0];
}

__global__ void k_scan2() {
    __shared__ int s[256];
    int t = threadIdx.x;
    int v = (t < NB_SCAN) ? g_partial[t] : 0;
    s[t] = v;
    __syncthreads();
#pragma unroll
    for (int d = 1; d < 256; d <<= 1) {
        int x = (t >= d) ? s[t - d] : 0;
        __syncthreads();
        s[t] += x;
        __syncthreads();
    }
    if (t < NB_SCAN) g_partial[t] = s[t] - v;  // exclusive
}

__global__ void k_scan3() {
    __shared__ int s[256];
    int t = threadIdx.x;
    int idx = blockIdx.x * 256 + t;
    int v = (idx < NN) ? g_rowcnt[idx] : 0;
    s[t] = v;
    __syncthreads();
#pragma unroll
    for (int d = 1; d < 256; d <<= 1) {
        int x = (t >= d) ? s[t - d] : 0;
        __syncthreads();
        s[t] += x;
        __syncthreads();
    }
    if (idx < NN) {
        int off = g_partial[blockIdx.x] + s[t] - v;
        g_rowoff[idx] = off;
        g_cursor[idx] = off;
        if (idx == NN - 1) g_rowoff[NN] = off + v;
    }
}

__global__ void k_scatter(const void* __restrict__ ei) {
    long i = (long)blockIdx.x * blockDim.x + threadIdx.x;
    if (i >= EE) return;
    int src, dst;
    load_edge(ei, i, src, dst);
    float e = g_esrc[src] + g_edst[dst];
    e = (e >= 0.f) ? e : 0.2f * e;
    int slot = atomicAdd(&g_cursor[dst], 1);
    g_csr_src[slot] = src;
    g_csr_e[slot] = e;
}

// ---------------- fused GAT aggregation: warp per dst node ----------------
__global__ __launch_bounds__(256) void k_agg(const float* __restrict__ b_gat) {
    int lane = threadIdx.x & 31;
    int n = blockIdx.x * 8 + (threadIdx.x >> 5);
    if (n >= NN) return;
    int beg = g_rowoff[n], end = g_rowoff[n + 1];

    // pass 1: segment max
    float m = -3.402823466e+38f;
    for (int i = beg + lane; i < end; i += 32) m = fmaxf(m, g_csr_e[i]);
#pragma unroll
    for (int o = 16; o; o >>= 1) m = fmaxf(m, __shfl_xor_sync(0xffffffffu, m, o));

    // pass 2: weighted aggregate
    float4 acc = make_float4(0.f, 0.f, 0.f, 0.f);
    float den = 0.f;
    for (int base = beg; base < end; base += 32) {
        int cnt = min(32, end - base);
        float ee = (base + lane < end) ? g_csr_e[base + lane] : 0.f;
        int ss = (base + lane < end) ? g_csr_src[base + lane] : 0;
        for (int j = 0; j < cnt; j++) {
            float e = __shfl_sync(0xffffffffu, ee, j);
            int s = __shfl_sync(0xffffffffu, ss, j);
            float w = __expf(e - m);
            den += w;
            float4 hv = ((const float4*)g_h)[(long)s * 32 + lane];
            acc.x = fmaf(w, hv.x, acc.x);
            acc.y = fmaf(w, hv.y, acc.y);
            acc.z = fmaf(w, hv.z, acc.z);
            acc.w = fmaf(w, hv.w, acc.w);
        }
    }
    float inv = 1.f / fmaxf(den, 1e-16f);
    float4 bg = ((const float4*)b_gat)[lane];
    float4 o;
    o.x = fmaxf(fmaf(acc.x, inv, bg.x), 0.f);
    o.y = fmaxf(fmaf(acc.y, inv, bg.y), 0.f);
    o.z = fmaxf(fmaf(acc.z, inv, bg.z), 0.f);
    o.w = fmaxf(fmaf(acc.w, inv, bg.w), 0.f);
    ((float4*)g_h0)[(long)n * 32 + lane] = o;
}

// ---------------- BN stats ----------------
__global__ void k_stats(const float* __restrict__ h, float* __restrict__ stats) {
    int t = threadIdx.x; // 128
    float s = 0.f, sq = 0.f;
    for (int n = blockIdx.x; n < NN; n += gridDim.x) {
        float v = h[(long)n * HH + t];
        s += v; sq += v * v;
    }
    atomicAdd(&stats[t], s);
    atomicAdd(&stats[HH + t], sq);
}

__global__ void k_finalize_bn(const float* __restrict__ stats,
                              const float* __restrict__ gamma, const float* __restrict__ beta,
                              float* __restrict__ scale, float* __restrict__ shift) {
    int t = threadIdx.x; // 128
    float mu = stats[t] / (float)NN;
    float var = stats[HH + t] / (float)NN - mu * mu;
    float sc = gamma[t] * rsqrtf(var + 1e-5f);
    scale[t] = sc;
    shift[t] = beta[t] - mu * sc;
}

// ---------------- final head ----------------
__global__ void k_final(const float* __restrict__ h2,
                        const float* __restrict__ W3, const float* __restrict__ b3,
                        float* __restrict__ out) {
    __shared__ float W3s[HH * AA];
    __shared__ float b3s[AA];
    int t = threadIdx.x; // 256
    for (int i = t; i < HH * AA; i += 256) W3s[i] = W3[i];
    if (t < AA) b3s[t] = b3[t];
    __syncthreads();
    int lane = t & 31;
    int n = blockIdx.x * 8 + (t >> 5);
    if (n >= NN) return;
    float hreg[4];
#pragma unroll
    for (int j = 0; j < 4; j++) {
        int c = j * 32 + lane;
        hreg[j] = fmaf(h2[(long)n * HH + c], g_scale2[c], g_shift2[c]);
    }
    float acc = b3s[lane];
#pragma unroll
    for (int k = 0; k < HH; k++) {
        float hv = __shfl_sync(0xffffffffu, hreg[k >> 5], k & 31);
        acc = fmaf(hv, W3s[k * AA + lane], acc);
    }
    float mx = acc;
#pragma unroll
    for (int o = 16; o; o >>= 1) mx = fmaxf(mx, __shfl_xor_sync(0xffffffffu, mx, o));
    float p = __expf(acc - mx);
    float s = p;
#pragma unroll
    for (int o = 16; o; o >>= 1) s += __shfl_xor_sync(0xffffffffu, s, o);
    out[(long)n * AA + lane] = p / s;
}

// ---------------- launch ----------------
extern "C" void kernel_launch(void* const* d_in, const int* in_sizes, int n_in,
                              void* d_out, int out_size) {
    const float* x     = (const float*)d_in[0];
    const void*  ei    = d_in[1];
    const float* W     = (const float*)d_in[2];
    const float* a_src = (const float*)d_in[3];
    const float* a_dst = (const float*)d_in[4];
    const float* b_gat = (const float*)d_in[5];
    const float* g0    = (const float*)d_in[6];
    const float* beta0 = (const float*)d_in[7];
    const float* W1    = (const float*)d_in[8];
    const float* b1    = (const float*)d_in[9];
    const float* W2    = (const float*)d_in[10];
    const float* b2    = (const float*)d_in[11];
    const float* g2    = (const float*)d_in[12];
    const float* beta2 = (const float*)d_in[13];
    const float* W3    = (const float*)d_in[14];
    const float* b3    = (const float*)d_in[15];
    float* out = (float*)d_out;

    float *p_h, *p_h0, *p_h1, *p_h2, *p_stats0, *p_stats2;
    float *p_scale0, *p_shift0, *p_scale2, *p_shift2, *p_bhi, *p_blo;
    cudaGetSymbolAddress((void**)&p_h, g_h);
    cudaGetSymbolAddress((void**)&p_h0, g_h0);
    cudaGetSymbolAddress((void**)&p_h1, g_h1);
    cudaGetSymbolAddress((void**)&p_h2, g_h2);
    cudaGetSymbolAddress((void**)&p_stats0, g_stats0);
    cudaGetSymbolAddress((void**)&p_stats2, g_stats2);
    cudaGetSymbolAddress((void**)&p_scale0, g_scale0);
    cudaGetSymbolAddress((void**)&p_shift0, g_shift0);
    cudaGetSymbolAddress((void**)&p_scale2, g_scale2);
    cudaGetSymbolAddress((void**)&p_shift2, g_shift2);
    cudaGetSymbolAddress((void**)&p_bhi, g_Bhi);
    cudaGetSymbolAddress((void**)&p_blo, g_Blo);

    const int gemmGrid = (NN + GBM - 1) / GBM;  // 391

    k_detect<<<1, 32>>>((const int*)ei);
    k_init<<<(NN + 255) / 256, 256>>>();

    // GEMM1: h = x @ W (K=256)
    k_splitB<<<(DIN * HH + 255) / 256, 256>>>(W, DIN * HH);
    k_gemm_tf32<<<gemmGrid, 256>>>(x, p_bhi, p_blo, p_h, NN, DIN,
                                   nullptr, nullptr, nullptr, 0);

    k_edot<<<(NN + 7) / 8, 256>>>(p_h, a_src, a_dst);

    // CSR build + fused aggregation
    k_hist<<<(EE + 255) / 256, 256>>>(ei);
    k_scan1<<<NB_SCAN, 256>>>();
    k_scan2<<<1, 256>>>();
    k_scan3<<<NB_SCAN, 256>>>();
    k_scatter<<<(EE + 255) / 256, 256>>>(ei);
    k_agg<<<(NN + 7) / 8, 256>>>(b_gat);

    k_stats<<<512, 128>>>(p_h0, p_stats0);
    k_finalize_bn<<<1, 128>>>(p_stats0, g0, beta0, p_scale0, p_shift0);

    // GEMM2: h1 = relu(bn0(h0) @ W1 + b1)
    k_splitB<<<(HH * HH + 255) / 256, 256>>>(W1, HH * HH);
    k_gemm_tf32<<<gemmGrid, 256>>>(p_h0, p_bhi, p_blo, p_h1, NN, HH,
                                   p_scale0, p_shift0, b1, 1);

    // GEMM3: h2 = relu(h1 @ W2 + b2)
    k_splitB<<<(HH * HH + 255) / 256, 256>>>(W2, HH * HH);
    k_gemm_tf32<<<gemmGrid, 256>>>(p_h1, p_bhi, p_blo, p_h2, NN, HH,
                                   nullptr, nullptr, b2, 1);

    k_stats<<<512, 128>>>(p_h2, p_stats2);
    k_finalize_bn<<<1, 128>>>(p_stats2, g2, beta2, p_scale2, p_shift2);
    k_final<<<(NN + 7) / 8, 256>>>(p_h2, W3, b3, out);
}

// round 6
// speedup vs baseline: 1.4283x; 1.0385x over previous
#include <cuda_runtime.h>
#include <cuda_bf16.h>
#include <cstdint>

#define NN 50000
#define EE 800000
#define DIN 256
#define HH 128
#define AA 32
#define NB_SCAN 196   // ceil(50000/256)

// ---------------- scratch (device globals) ----------------
__device__ float g_h   [(size_t)NN * HH];
__device__ float g_h0  [(size_t)NN * HH];
__device__ float g_h1  [(size_t)NN * HH];
__device__ float g_h2  [(size_t)NN * HH];
__device__ float g_esrc[NN];
__device__ float g_edst[NN];
__device__ int   g_rowcnt[NN];
__device__ int   g_rowoff[NN + 1];
__device__ int   g_cursor[NN];
__device__ int   g_partial[256];
__device__ int   g_csr_src[EE];
__device__ float g_csr_e[EE];
__device__ float g_stats0[2 * HH];
__device__ float g_stats2[2 * HH];
__device__ float g_scale0[HH], g_shift0[HH];
__device__ float g_scale2[HH], g_shift2[HH];
__device__ float2 g_Bhl[(DIN + HH + HH) * HH];   // interleaved (hi,lo) weights
__device__ int   g_is64;

// ---------------- helpers ----------------
__device__ __forceinline__ void load_edge(const void* ei, long i, int& src, int& dst) {
    if (g_is64) {
        const long long* p = (const long long*)ei;
        src = (int)p[i]; dst = (int)p[(long)EE + i];
    } else {
        const int* p = (const int*)ei;
        src = p[i]; dst = p[EE + i];
    }
}
__device__ __forceinline__ void tf32_split(float v, float& hi, float& lo) {
    unsigned h;
    asm("cvt.rna.tf32.f32 %0, %1;" : "=r"(h) : "f"(v));
    float fh = __uint_as_float(h);
    float r = v - fh;
    unsigned l;
    asm("cvt.rna.tf32.f32 %0, %1;" : "=r"(l) : "f"(r));
    hi = fh; lo = __uint_as_float(l);
}
__device__ __forceinline__ void mma_tf32(float* c, const unsigned* a, unsigned b0, unsigned b1) {
    asm volatile(
        "mma.sync.aligned.m16n8k8.row.col.f32.tf32.tf32.f32 "
        "{%0,%1,%2,%3}, {%4,%5,%6,%7}, {%8,%9}, {%0,%1,%2,%3};"
        : "+f"(c[0]), "+f"(c[1]), "+f"(c[2]), "+f"(c[3])
        : "r"(a[0]), "r"(a[1]), "r"(a[2]), "r"(a[3]), "r"(b0), "r"(b1));
}
__device__ __forceinline__ void cp16(uint32_t saddr, const void* gaddr) {
    asm volatile("cp.async.ca.shared.global [%0], [%1], 16;" :: "r"(saddr), "l"(gaddr));
}

// ---------------- init (+dtype detect) ----------------
__global__ void k_init(const int* ei_words) {
    int idx = blockIdx.x * blockDim.x + threadIdx.x;
    if (idx == 0) {
        int nz = 0;
        for (int i = 1; i < 2048; i += 2) nz += (ei_words[i] != 0);
        g_is64 = (nz == 0) ? 1 : 0;
    }
    if (idx < NN) {
        g_rowcnt[idx] = 0;
        g_esrc[idx] = 0.f;
        g_edst[idx] = 0.f;
    }
    if (idx < 2 * HH) { g_stats0[idx] = 0.f; g_stats2[idx] = 0.f; }
}

// split all three weight matrices into interleaved (hi,lo)
__global__ void k_splitAll(const float* __restrict__ W, const float* __restrict__ W1,
                           const float* __restrict__ W2) {
    int i = blockIdx.x * 256 + threadIdx.x;
    const int n0 = DIN * HH;          // 32768
    const int n1 = n0 + HH * HH;      // 49152
    const int n2 = n1 + HH * HH;      // 65536
    if (i >= n2) return;
    float v;
    if (i < n0) v = W[i];
    else if (i < n1) v = W1[i - n0];
    else v = W2[i - n1];
    float hi, lo;
    tf32_split(v, hi, lo);
    g_Bhl[i] = make_float2(hi, lo);
}

// ------------- 3xTF32 tensor-core GEMM, float2-packed smem, cp.async B, 2-stage -------------
#define GBM 128
#define GBN 128
#define GBK 16
#define AROW (GBM + 4)   // float2 units; stride = 264 floats -> 8 banks per k-row

__global__ __launch_bounds__(256, 2) void k_gemm_tf32(
    const float* __restrict__ A,
    const float2* __restrict__ Bhl,
    float* __restrict__ C, int M, int K,
    const float* __restrict__ in_scale, const float* __restrict__ in_shift,
    const float* __restrict__ bias, int do_relu,
    const float* __restrict__ a_src, const float* __restrict__ a_dst)
{
    extern __shared__ float2 smem[];
    float2 (*As)[GBK][AROW] = reinterpret_cast<float2 (*)[GBK][AROW]>(smem);
    float2 (*Bs)[GBK][AROW] = reinterpret_cast<float2 (*)[GBK][AROW]>(smem + 2 * GBK * AROW);

    const int tid = threadIdx.x;
    const int warp = tid >> 5, lane = tid & 31;
    const int g = lane >> 2, q = lane & 3;
    const int wm = (warp & 3) * 32;
    const int wn = (warp >> 2) * 64;
    const int blockRow = blockIdx.x * GBM;

    const int arow = tid >> 1;            // 0..127
    const int acol = (tid & 1) * 8;       // 0 or 8
    const int bk = tid >> 4;              // 0..15
    const int bn = (tid & 15) * 8;        // 0..120

    const int aRowGlobal = blockRow + arow;
    const bool aValid = aRowGlobal < M;

    float c[2][8][4];
#pragma unroll
    for (int mt = 0; mt < 2; mt++)
#pragma unroll
        for (int nt = 0; nt < 8; nt++)
#pragma unroll
            for (int j = 0; j < 4; j++) c[mt][nt][j] = 0.f;

    float av[8];

    // ---- prologue: stage tile 0 ----
    {
        const int k0 = 0;
        uint32_t sB = (uint32_t)__cvta_generic_to_shared(&Bs[0][bk][bn]);
        const float2* gB = Bhl + (size_t)(k0 + bk) * GBN + bn;
#pragma unroll
        for (int j = 0; j < 4; j++) cp16(sB + j * 16, gB + j * 2);
        asm volatile("cp.async.commit_group;");

#pragma unroll
        for (int j = 0; j < 8; j++) av[j] = 0.f;
        if (aValid) {
            float4 v0 = *(const float4*)&A[(long)aRowGlobal * K + k0 + acol];
            float4 v1 = *(const float4*)&A[(long)aRowGlobal * K + k0 + acol + 4];
            av[0] = v0.x; av[1] = v0.y; av[2] = v0.z; av[3] = v0.w;
            av[4] = v1.x; av[5] = v1.y; av[6] = v1.z; av[7] = v1.w;
        }
        if (in_scale) {
#pragma unroll
            for (int j = 0; j < 8; j++)
                av[j] = fmaf(av[j], in_scale[k0 + acol + j], in_shift[k0 + acol + j]);
        }
#pragma unroll
        for (int j = 0; j < 8; j++) {
            float hi, lo;
            tf32_split(av[j], hi, lo);
            As[0][acol + j][arow] = make_float2(hi, lo);
        }
        asm volatile("cp.async.wait_group 0;" ::: "memory");
        __syncthreads();
    }

    const int ntiles = K / GBK;
    for (int t = 0; t < ntiles; t++) {
        const int cur = t & 1, nxt = cur ^ 1;

        // ---- issue loads for tile t+1 ----
        const bool more = (t + 1 < ntiles);
        if (more) {
            const int k0 = (t + 1) * GBK;
            uint32_t sB = (uint32_t)__cvta_generic_to_shared(&Bs[nxt][bk][bn]);
            const float2* gB = Bhl + (size_t)(k0 + bk) * GBN + bn;
#pragma unroll
            for (int j = 0; j < 4; j++) cp16(sB + j * 16, gB + j * 2);
            asm volatile("cp.async.commit_group;");

#pragma unroll
            for (int j = 0; j < 8; j++) av[j] = 0.f;
            if (aValid) {
                float4 v0 = *(const float4*)&A[(long)aRowGlobal * K + k0 + acol];
                float4 v1 = *(const float4*)&A[(long)aRowGlobal * K + k0 + acol + 4];
                av[0] = v0.x; av[1] = v0.y; av[2] = v0.z; av[3] = v0.w;
                av[4] = v1.x; av[5] = v1.y; av[6] = v1.z; av[7] = v1.w;
            }
            if (in_scale) {
#pragma unroll
                for (int j = 0; j < 8; j++)
                    av[j] = fmaf(av[j], in_scale[k0 + acol + j], in_shift[k0 + acol + j]);
            }
        }

        // ---- MMA on current tile ----
#pragma unroll
        for (int ks = 0; ks < GBK; ks += 8) {
            unsigned ah[2][4], al[2][4];
#pragma unroll
            for (int mt = 0; mt < 2; mt++) {
                int m = wm + mt * 16;
                float2 a00 = As[cur][ks + q][m + g];
                float2 a01 = As[cur][ks + q][m + g + 8];
                float2 a10 = As[cur][ks + q + 4][m + g];
                float2 a11 = As[cur][ks + q + 4][m + g + 8];
                ah[mt][0] = __float_as_uint(a00.x); al[mt][0] = __float_as_uint(a00.y);
                ah[mt][1] = __float_as_uint(a01.x); al[mt][1] = __float_as_uint(a01.y);
                ah[mt][2] = __float_as_uint(a10.x); al[mt][2] = __float_as_uint(a10.y);
                ah[mt][3] = __float_as_uint(a11.x); al[mt][3] = __float_as_uint(a11.y);
            }
#pragma unroll
            for (int nt = 0; nt < 8; nt++) {
                int n = wn + nt * 8 + g;
                float2 b0 = Bs[cur][ks + q][n];
                float2 b1 = Bs[cur][ks + q + 4][n];
                unsigned bh0 = __float_as_uint(b0.x), bl0 = __float_as_uint(b0.y);
                unsigned bh1 = __float_as_uint(b1.x), bl1 = __float_as_uint(b1.y);
#pragma unroll
                for (int mt = 0; mt < 2; mt++) {
                    mma_tf32(c[mt][nt], ah[mt], bh0, bh1);
                    mma_tf32(c[mt][nt], al[mt], bh0, bh1);
                    mma_tf32(c[mt][nt], ah[mt], bl0, bl1);
                }
            }
        }

        if (more) {
#pragma unroll
            for (int j = 0; j < 8; j++) {
                float hi, lo;
                tf32_split(av[j], hi, lo);
                As[nxt][acol + j][arow] = make_float2(hi, lo);
            }
            asm volatile("cp.async.wait_group 0;" ::: "memory");
            __syncthreads();
        }
    }

    // ---- epilogue (+ optional fused e_src/e_dst dots) ----
    float ps[2][2] = {{0.f, 0.f}, {0.f, 0.f}};
    float pd[2][2] = {{0.f, 0.f}, {0.f, 0.f}};
    const bool do_edot = (a_src != nullptr);

#pragma unroll
    for (int mt = 0; mt < 2; mt++) {
#pragma unroll
        for (int nt = 0; nt < 8; nt++) {
            int col = wn + nt * 8 + q * 2;
            float b0 = 0.f, b1 = 0.f;
            if (bias) { b0 = bias[col]; b1 = bias[col + 1]; }
            float as0 = 0.f, as1 = 0.f, ad0 = 0.f, ad1 = 0.f;
            if (do_edot) {
                as0 = a_src[col]; as1 = a_src[col + 1];
                ad0 = a_dst[col]; ad1 = a_dst[col + 1];
            }
#pragma unroll
            for (int half = 0; half < 2; half++) {
                int row = blockRow + wm + mt * 16 + g + half * 8;
                if (row < M) {
                    float v0 = c[mt][nt][half * 2 + 0] + b0;
                    float v1 = c[mt][nt][half * 2 + 1] + b1;
                    if (do_relu) { v0 = fmaxf(v0, 0.f); v1 = fmaxf(v1, 0.f); }
                    if (do_edot) {
                        ps[mt][half] += v0 * as0 + v1 * as1;
                        pd[mt][half] += v0 * ad0 + v1 * ad1;
                    }
                    float2 o; o.x = v0; o.y = v1;
                    *(float2*)&C[(long)row * GBN + col] = o;
                }
            }
        }
    }

    if (do_edot) {
        // reduce over q (lanes g*4+q: xor 1, 2 stay in quad)
#pragma unroll
        for (int mt = 0; mt < 2; mt++)
#pragma unroll
            for (int half = 0; half < 2; half++) {
                float s = ps[mt][half], d = pd[mt][half];
                s += __shfl_xor_sync(0xffffffffu, s, 1);
                s += __shfl_xor_sync(0xffffffffu, s, 2);
                d += __shfl_xor_sync(0xffffffffu, d, 1);
                d += __shfl_xor_sync(0xffffffffu, d, 2);
                if (q == 0) {
                    int row = blockRow + wm + mt * 16 + g + half * 8;
                    if (row < M) {
                        atomicAdd(&g_esrc[row], s);
                        atomicAdd(&g_edst[row], d);
                    }
                }
            }
    }
}

// ---------------- CSR build ----------------
__global__ void k_hist(const void* __restrict__ ei) {
    long i = (long)blockIdx.x * blockDim.x + threadIdx.x;
    if (i >= EE) return;
    int src, dst;
    load_edge(ei, i, src, dst);
    atomicAdd(&g_rowcnt[dst], 1);
}

__global__ void k_scan1() {
    __shared__ int s[256];
    int idx = blockIdx.x * 256 + threadIdx.x;
    int v = (idx < NN) ? g_rowcnt[idx] : 0;
    s[threadIdx.x] = v;
    __syncthreads();
    for (int o = 128; o; o >>= 1) {
        if (threadIdx.x < o) s[threadIdx.x] += s[threadIdx.x + o];
        __syncthreads();
    }
    if (threadIdx.x == 0) g_partial[blockIdx.x] = s[0];
}

__global__ void k_scan2() {
    __shared__ int s[256];
    int t = threadIdx.x;
    int v = (t < NB_SCAN) ? g_partial[t] : 0;
    s[t] = v;
    __syncthreads();
#pragma unroll
    for (int d = 1; d < 256; d <<= 1) {
        int x = (t >= d) ? s[t - d] : 0;
        __syncthreads();
        s[t] += x;
        __syncthreads();
    }
    if (t < NB_SCAN) g_partial[t] = s[t] - v;  // exclusive
}

__global__ void k_scan3() {
    __shared__ int s[256];
    int t = threadIdx.x;
    int idx = blockIdx.x * 256 + t;
    int v = (idx < NN) ? g_rowcnt[idx] : 0;
    s[t] = v;
    __syncthreads();
#pragma unroll
    for (int d = 1; d < 256; d <<= 1) {
        int x = (t >= d) ? s[t - d] : 0;
        __syncthreads();
        s[t] += x;
        __syncthreads();
    }
    if (idx < NN) {
        int off = g_partial[blockIdx.x] + s[t] - v;
        g_rowoff[idx] = off;
        g_cursor[idx] = off;
        if (idx == NN - 1) g_rowoff[NN] = off + v;
    }
}

__global__ void k_scatter(const void* __restrict__ ei) {
    long i = (long)blockIdx.x * blockDim.x + threadIdx.x;
    if (i >= EE) return;
    int src, dst;
    load_edge(ei, i, src, dst);
    float e = g_esrc[src] + g_edst[dst];
    e = (e >= 0.f) ? e : 0.2f * e;
    int slot = atomicAdd(&g_cursor[dst], 1);
    g_csr_src[slot] = src;
    g_csr_e[slot] = e;
}

// -------- fused GAT aggregation (warp/node) + bn0 stats --------
__global__ __launch_bounds__(256) void k_agg(const float* __restrict__ b_gat) {
    __shared__ float s_sum[HH];
    __shared__ float s_sq[HH];
    int tid = threadIdx.x;
    if (tid < HH) { s_sum[tid] = 0.f; s_sq[tid] = 0.f; }
    __syncthreads();

    int lane = tid & 31;
    int n = blockIdx.x * 8 + (tid >> 5);
    if (n < NN) {
        int beg = g_rowoff[n], end = g_rowoff[n + 1];

        float m = -3.402823466e+38f;
        for (int i = beg + lane; i < end; i += 32) m = fmaxf(m, g_csr_e[i]);
#pragma unroll
        for (int o = 16; o; o >>= 1) m = fmaxf(m, __shfl_xor_sync(0xffffffffu, m, o));

        float4 acc = make_float4(0.f, 0.f, 0.f, 0.f);
        float den = 0.f;
        for (int base = beg; base < end; base += 32) {
            int cnt = min(32, end - base);
            float ee = (base + lane < end) ? g_csr_e[base + lane] : 0.f;
            int ss = (base + lane < end) ? g_csr_src[base + lane] : 0;
            int j = 0;
            for (; j + 4 <= cnt; j += 4) {
                float e0 = __shfl_sync(0xffffffffu, ee, j);
                float e1 = __shfl_sync(0xffffffffu, ee, j + 1);
                float e2 = __shfl_sync(0xffffffffu, ee, j + 2);
                float e3 = __shfl_sync(0xffffffffu, ee, j + 3);
                int s0 = __shfl_sync(0xffffffffu, ss, j);
                int s1 = __shfl_sync(0xffffffffu, ss, j + 1);
                int s2 = __shfl_sync(0xffffffffu, ss, j + 2);
                int s3 = __shfl_sync(0xffffffffu, ss, j + 3);
                float4 h0v = ((const float4*)g_h)[(long)s0 * 32 + lane];
                float4 h1v = ((const float4*)g_h)[(long)s1 * 32 + lane];
                float4 h2v = ((const float4*)g_h)[(long)s2 * 32 + lane];
                float4 h3v = ((const float4*)g_h)[(long)s3 * 32 + lane];
                float w0 = __expf(e0 - m), w1 = __expf(e1 - m);
                float w2 = __expf(e2 - m), w3 = __expf(e3 - m);
                den += (w0 + w1) + (w2 + w3);
                acc.x = fmaf(w0, h0v.x, fmaf(w1, h1v.x, fmaf(w2, h2v.x, fmaf(w3, h3v.x, acc.x))));
                acc.y = fmaf(w0, h0v.y, fmaf(w1, h1v.y, fmaf(w2, h2v.y, fmaf(w3, h3v.y, acc.y))));
                acc.z = fmaf(w0, h0v.z, fmaf(w1, h1v.z, fmaf(w2, h2v.z, fmaf(w3, h3v.z, acc.z))));
                acc.w = fmaf(w0, h0v.w, fmaf(w1, h1v.w, fmaf(w2, h2v.w, fmaf(w3, h3v.w, acc.w))));
            }
            for (; j < cnt; j++) {
                float e = __shfl_sync(0xffffffffu, ee, j);
                int s = __shfl_sync(0xffffffffu, ss, j);
                float w = __expf(e - m);
                den += w;
                float4 hv = ((const float4*)g_h)[(long)s * 32 + lane];
                acc.x = fmaf(w, hv.x, acc.x);
                acc.y = fmaf(w, hv.y, acc.y);
                acc.z = fmaf(w, hv.z, acc.z);
                acc.w = fmaf(w, hv.w, acc.w);
            }
        }
        float inv = 1.f / fmaxf(den, 1e-16f);
        float4 bg = ((const float4*)b_gat)[lane];
        float4 o;
        o.x = fmaxf(fmaf(acc.x, inv, bg.x), 0.f);
        o.y = fmaxf(fmaf(acc.y, inv, bg.y), 0.f);
        o.z = fmaxf(fmaf(acc.z, inv, bg.z), 0.f);
        o.w = fmaxf(fmaf(acc.w, inv, bg.w), 0.f);
        ((float4*)g_h0)[(long)n * 32 + lane] = o;

        int c0 = lane * 4;
        atomicAdd(&s_sum[c0 + 0], o.x); atomicAdd(&s_sq[c0 + 0], o.x * o.x);
        atomicAdd(&s_sum[c0 + 1], o.y); atomicAdd(&s_sq[c0 + 1], o.y * o.y);
        atomicAdd(&s_sum[c0 + 2], o.z); atomicAdd(&s_sq[c0 + 2], o.z * o.z);
        atomicAdd(&s_sum[c0 + 3], o.w); atomicAdd(&s_sq[c0 + 3], o.w * o.w);
    }
    __syncthreads();
    if (tid < HH) {
        atomicAdd(&g_stats0[tid], s_sum[tid]);
        atomicAdd(&g_stats0[HH + tid], s_sq[tid]);
    }
}

// ---------------- BN stats (for h2) ----------------
__global__ void k_stats(const float* __restrict__ h, float* __restrict__ stats) {
    int t = threadIdx.x; // 128
    float s = 0.f, sq = 0.f;
    for (int n = blockIdx.x; n < NN; n += gridDim.x) {
        float v = h[(long)n * HH + t];
        s += v; sq += v * v;
    }
    atomicAdd(&stats[t], s);
    atomicAdd(&stats[HH + t], sq);
}

__global__ void k_finalize_bn(const float* __restrict__ stats,
                              const float* __restrict__ gamma, const float* __restrict__ beta,
                              float* __restrict__ scale, float* __restrict__ shift) {
    int t = threadIdx.x; // 128
    float mu = stats[t] / (float)NN;
    float var = stats[HH + t] / (float)NN - mu * mu;
    float sc = gamma[t] * rsqrtf(var + 1e-5f);
    scale[t] = sc;
    shift[t] = beta[t] - mu * sc;
}

// ---------------- final head ----------------
__global__ void k_final(const float* __restrict__ h2,
                        const float* __restrict__ W3, const float* __restrict__ b3,
                        float* __restrict__ out) {
    __shared__ float W3s[HH * AA];
    __shared__ float b3s[AA];
    int t = threadIdx.x; // 256
    for (int i = t; i < HH * AA; i += 256) W3s[i] = W3[i];
    if (t < AA) b3s[t] = b3[t];
    __syncthreads();
    int lane = t & 31;
    int n = blockIdx.x * 8 + (t >> 5);
    if (n >= NN) return;
    float hreg[4];
#pragma unroll
    for (int j = 0; j < 4; j++) {
        int c = j * 32 + lane;
        hreg[j] = fmaf(h2[(long)n * HH + c], g_scale2[c], g_shift2[c]);
    }
    float acc = b3s[lane];
#pragma unroll
    for (int k = 0; k < HH; k++) {
        float hv = __shfl_sync(0xffffffffu, hreg[k >> 5], k & 31);
        acc = fmaf(hv, W3s[k * AA + lane], acc);
    }
    float mx = acc;
#pragma unroll
    for (int o = 16; o; o >>= 1) mx = fmaxf(mx, __shfl_xor_sync(0xffffffffu, mx, o));
    float p = __expf(acc - mx);
    float s = p;
#pragma unroll
    for (int o = 16; o; o >>= 1) s += __shfl_xor_sync(0xffffffffu, s, o);
    out[(long)n * AA + lane] = p / s;
}

// ---------------- launch ----------------
extern "C" void kernel_launch(void* const* d_in, const int* in_sizes, int n_in,
                              void* d_out, int out_size) {
    const float* x     = (const float*)d_in[0];
    const void*  ei    = d_in[1];
    const float* W     = (const float*)d_in[2];
    const float* a_src = (const float*)d_in[3];
    const float* a_dst = (const float*)d_in[4];
    const float* b_gat = (const float*)d_in[5];
    const float* g0    = (const float*)d_in[6];
    const float* beta0 = (const float*)d_in[7];
    const float* W1    = (const float*)d_in[8];
    const float* b1    = (const float*)d_in[9];
    const float* W2    = (const float*)d_in[10];
    const float* b2    = (const float*)d_in[11];
    const float* g2    = (const float*)d_in[12];
    const float* beta2 = (const float*)d_in[13];
    const float* W3    = (const float*)d_in[14];
    const float* b3    = (const float*)d_in[15];
    float* out = (float*)d_out;

    float *p_h, *p_h0, *p_h1, *p_h2, *p_stats0, *p_stats2;
    float *p_scale0, *p_shift0, *p_scale2, *p_shift2;
    float2 *p_bhl;
    cudaGetSymbolAddress((void**)&p_h, g_h);
    cudaGetSymbolAddress((void**)&p_h0, g_h0);
    cudaGetSymbolAddress((void**)&p_h1, g_h1);
    cudaGetSymbolAddress((void**)&p_h2, g_h2);
    cudaGetSymbolAddress((void**)&p_stats0, g_stats0);
    cudaGetSymbolAddress((void**)&p_stats2, g_stats2);
    cudaGetSymbolAddress((void**)&p_scale0, g_scale0);
    cudaGetSymbolAddress((void**)&p_shift0, g_shift0);
    cudaGetSymbolAddress((void**)&p_scale2, g_scale2);
    cudaGetSymbolAddress((void**)&p_shift2, g_shift2);
    cudaGetSymbolAddress((void**)&p_bhl, g_Bhl);

    const int gemmGrid = (NN + GBM - 1) / GBM;  // 391
    const int SMEM_GEMM = 4 * GBK * (GBM + 4) * (int)sizeof(float2);  // 67584

    static int s_attr_set = 0;
    if (!s_attr_set) {
        cudaFuncSetAttribute(k_gemm_tf32, cudaFuncAttributeMaxDynamicSharedMemorySize, SMEM_GEMM);
        s_attr_set = 1;
    }

    k_init<<<(NN + 255) / 256, 256>>>((const int*)ei);
    k_splitAll<<<((DIN + 2 * HH) * HH + 255) / 256, 256>>>(W, W1, W2);

    // GEMM1: h = x @ W (K=256), fused e_src/e_dst dots
    k_gemm_tf32<<<gemmGrid, 256, SMEM_GEMM>>>(x, p_bhl, p_h, NN, DIN,
                                              nullptr, nullptr, nullptr, 0, a_src, a_dst);

    // CSR build + fused aggregation (+bn0 stats)
    k_hist<<<(EE + 255) / 256, 256>>>(ei);
    k_scan1<<<NB_SCAN, 256>>>();
    k_scan2<<<1, 256>>>();
    k_scan3<<<NB_SCAN, 256>>>();
    k_scatter<<<(EE + 255) / 256, 256>>>(ei);
    k_agg<<<(NN + 7) / 8, 256>>>(b_gat);

    k_finalize_bn<<<1, 128>>>(p_stats0, g0, beta0, p_scale0, p_shift0);

    // GEMM2: h1 = relu(bn0(h0) @ W1 + b1)
    k_gemm_tf32<<<gemmGrid, 256, SMEM_GEMM>>>(p_h0, p_bhl + DIN * HH, p_h1, NN, HH,
                                              p_scale0, p_shift0, b1, 1, nullptr, nullptr);

    // GEMM3: h2 = relu(h1 @ W2 + b2)
    k_gemm_tf32<<<gemmGrid, 256, SMEM_GEMM>>>(p_h1, p_bhl + (DIN + HH) * HH, p_h2, NN, HH,
                                              nullptr, nullptr, b2, 1, nullptr, nullptr);

    k_stats<<<512, 128>>>(p_h2, p_stats2);
    k_finalize_bn<<<1, 128>>>(p_stats2, g2, beta2, p_scale2, p_shift2);
    k_final<<<(NN + 7) / 8, 256>>>(p_h2, W3, b3, out);
}